// round 1
// baseline (speedup 1.0000x reference)
#include <cuda_runtime.h>
#include <math.h>

#define BATCH 8192
#define FEAT  128
#define NROWS (2 * BATCH)
#define MARGINF 0.3f

#define BM 128
#define BN 128
#define BK 16
#define TM 8
#define TN 8

// Scratch (device globals: no allocation allowed in kernel_launch)
__device__ float g_sq[NROWS];        // squared norms of all rows
__device__ int   g_ap_row[BATCH];    // max pos d2 (float bits) for rows 0..B-1
__device__ int   g_an_row[BATCH];    // min neg d2
__device__ int   g_ap_col[BATCH];    // max pos d2 for rows B..2B-1 (columns of D)
__device__ int   g_an_col[BATCH];    // min neg d2

// ---------------------------------------------------------------------------
// Kernel A: per-row squared norms + init of mining arrays
// grid: NROWS/8 blocks of 256 threads; one warp per row (128 floats = 32 float4)
// ---------------------------------------------------------------------------
__global__ void prep_kernel(const float* __restrict__ inp) {
    int row  = blockIdx.x * 8 + (threadIdx.x >> 5);
    int lane = threadIdx.x & 31;
    const float4* p = reinterpret_cast<const float4*>(inp + (size_t)row * FEAT);
    float4 v = p[lane];
    float s = v.x * v.x + v.y * v.y + v.z * v.z + v.w * v.w;
#pragma unroll
    for (int o = 16; o; o >>= 1) s += __shfl_down_sync(0xffffffffu, s, o);
    if (lane == 0) g_sq[row] = s;

    int idx = blockIdx.x * blockDim.x + threadIdx.x;
    if (idx < BATCH) {
        g_ap_row[idx] = 0;            // 0.0f bits  (identity for max of d2 >= 0)
        g_an_row[idx] = 0x7f800000;   // +inf bits  (identity for min)
        g_ap_col[idx] = 0;
        g_an_col[idx] = 0x7f800000;
    }
}

// ---------------------------------------------------------------------------
// Kernel B: cross-modal distance GEMM + fused masked hard mining on d2.
// D2[i][j] = ||x0_i||^2 + ||x1_j||^2 - 2 x0_i . x1_j   (i,j in [0,B))
// Row reductions -> first-half rows; column reductions -> second-half rows.
// ---------------------------------------------------------------------------
__global__ __launch_bounds__(256) void dist_kernel(const float* __restrict__ X,
                                                   const int* __restrict__ T) {
    __shared__ float As[BK][BM + 4];
    __shared__ float Bs[BK][BN + 4];
    __shared__ int s_ap_row[BM], s_an_row[BM], s_ap_col[BN], s_an_col[BN];
    __shared__ int s_t0[BM], s_t1[BN];

    const int tid = threadIdx.x;
    const int m0  = blockIdx.y * BM;
    const int n0  = blockIdx.x * BN;

    if (tid < 128) {
        s_ap_row[tid] = 0;          s_an_row[tid] = 0x7f800000;
        s_ap_col[tid] = 0;          s_an_col[tid] = 0x7f800000;
        s_t0[tid] = T[m0 + tid];
        s_t1[tid] = T[BATCH + n0 + tid];
    }

    const float* Ag = X + (size_t)m0 * FEAT;
    const float* Bg = X + (size_t)(BATCH + n0) * FEAT;

    const int tr = tid >> 4;   // 0..15
    const int tc = tid & 15;   // 0..15

    float acc[TM][TN];
#pragma unroll
    for (int i = 0; i < TM; i++)
#pragma unroll
        for (int j = 0; j < TN; j++) acc[i][j] = 0.f;

    const int lrow = tid >> 2;  // 0..63
    const int lq   = tid & 3;   // which float4 of the 16-wide K slab

    for (int kk = 0; kk < FEAT; kk += BK) {
        float4 a0 = *reinterpret_cast<const float4*>(Ag + (size_t)lrow        * FEAT + kk + lq * 4);
        float4 a1 = *reinterpret_cast<const float4*>(Ag + (size_t)(lrow + 64) * FEAT + kk + lq * 4);
        float4 b0 = *reinterpret_cast<const float4*>(Bg + (size_t)lrow        * FEAT + kk + lq * 4);
        float4 b1 = *reinterpret_cast<const float4*>(Bg + (size_t)(lrow + 64) * FEAT + kk + lq * 4);

        __syncthreads();  // previous iteration's reads (and first-iter s_* init) done
        As[lq * 4 + 0][lrow] = a0.x;  As[lq * 4 + 1][lrow] = a0.y;
        As[lq * 4 + 2][lrow] = a0.z;  As[lq * 4 + 3][lrow] = a0.w;
        As[lq * 4 + 0][lrow + 64] = a1.x;  As[lq * 4 + 1][lrow + 64] = a1.y;
        As[lq * 4 + 2][lrow + 64] = a1.z;  As[lq * 4 + 3][lrow + 64] = a1.w;
        Bs[lq * 4 + 0][lrow] = b0.x;  Bs[lq * 4 + 1][lrow] = b0.y;
        Bs[lq * 4 + 2][lrow] = b0.z;  Bs[lq * 4 + 3][lrow] = b0.w;
        Bs[lq * 4 + 0][lrow + 64] = b1.x;  Bs[lq * 4 + 1][lrow + 64] = b1.y;
        Bs[lq * 4 + 2][lrow + 64] = b1.z;  Bs[lq * 4 + 3][lrow + 64] = b1.w;
        __syncthreads();

#pragma unroll
        for (int k = 0; k < BK; k++) {
            float a[TM], b[TN];
#pragma unroll
            for (int i = 0; i < TM; i += 4)
                *reinterpret_cast<float4*>(&a[i]) =
                    *reinterpret_cast<const float4*>(&As[k][tr * TM + i]);
#pragma unroll
            for (int j = 0; j < TN; j += 4)
                *reinterpret_cast<float4*>(&b[j]) =
                    *reinterpret_cast<const float4*>(&Bs[k][tc * TN + j]);
#pragma unroll
            for (int i = 0; i < TM; i++)
#pragma unroll
                for (int j = 0; j < TN; j++) acc[i][j] = fmaf(a[i], b[j], acc[i][j]);
        }
    }

    // ---- epilogue: d2 + masked mining on d2 (sqrt deferred; sqrt is monotone) ----
    float sqm[TM], sqn[TN];
    int   tm[TM], tn[TN];
#pragma unroll
    for (int i = 0; i < TM; i++) {
        sqm[i] = g_sq[m0 + tr * TM + i];
        tm[i]  = s_t0[tr * TM + i];
    }
#pragma unroll
    for (int j = 0; j < TN; j++) {
        sqn[j] = g_sq[BATCH + n0 + tc * TN + j];
        tn[j]  = s_t1[tc * TN + j];
    }

    float apr[TM], anr[TM], apc[TN], anc[TN];
#pragma unroll
    for (int i = 0; i < TM; i++) { apr[i] = 0.f; anr[i] = __int_as_float(0x7f800000); }
#pragma unroll
    for (int j = 0; j < TN; j++) { apc[j] = 0.f; anc[j] = __int_as_float(0x7f800000); }

#pragma unroll
    for (int i = 0; i < TM; i++) {
#pragma unroll
        for (int j = 0; j < TN; j++) {
            float d2 = fmaxf(fmaf(-2.f, acc[i][j], sqm[i] + sqn[j]), 0.f);
            bool same = (tm[i] == tn[j]);
            if (same) {
                apr[i] = fmaxf(apr[i], d2);
                apc[j] = fmaxf(apc[j], d2);
            } else {
                anr[i] = fminf(anr[i], d2);
                anc[j] = fminf(anc[j], d2);
            }
        }
    }

    // block-level reduction via shared int atomics (d2 >= 0 -> bit order == float order)
#pragma unroll
    for (int i = 0; i < TM; i++) {
        atomicMax(&s_ap_row[tr * TM + i], __float_as_int(apr[i]));
        atomicMin(&s_an_row[tr * TM + i], __float_as_int(anr[i]));
    }
#pragma unroll
    for (int j = 0; j < TN; j++) {
        atomicMax(&s_ap_col[tc * TN + j], __float_as_int(apc[j]));
        atomicMin(&s_an_col[tc * TN + j], __float_as_int(anc[j]));
    }
    __syncthreads();

    if (tid < 128) {
        if (s_ap_row[tid] != 0)          atomicMax(&g_ap_row[m0 + tid], s_ap_row[tid]);
        if (s_an_row[tid] != 0x7f800000) atomicMin(&g_an_row[m0 + tid], s_an_row[tid]);
        if (s_ap_col[tid] != 0)          atomicMax(&g_ap_col[n0 + tid], s_ap_col[tid]);
        if (s_an_col[tid] != 0x7f800000) atomicMin(&g_an_col[n0 + tid], s_an_col[tid]);
    }
}

// ---------------------------------------------------------------------------
// Kernel C: final loss / correct reduction (single block)
// ---------------------------------------------------------------------------
__global__ void finalize_kernel(float* __restrict__ out) {
    __shared__ float red[256];
    __shared__ int   redc[256];
    float lsum = 0.f;
    int   cnt  = 0;
    for (int i = threadIdx.x; i < NROWS; i += 256) {
        float apd2, and2;
        if (i < BATCH) {
            apd2 = __int_as_float(g_ap_row[i]);
            and2 = __int_as_float(g_an_row[i]);
        } else {
            apd2 = __int_as_float(g_ap_col[i - BATCH]);
            and2 = __int_as_float(g_an_col[i - BATCH]);
        }
        float ap = sqrtf(fmaxf(apd2, 1e-12f));
        float an = sqrtf(fmaxf(and2, 1e-12f));
        lsum += fmaxf(ap - an + MARGINF, 0.f);
        cnt  += (an >= ap) ? 1 : 0;
    }
    red[threadIdx.x]  = lsum;
    redc[threadIdx.x] = cnt;
    __syncthreads();
    for (int s = 128; s; s >>= 1) {
        if (threadIdx.x < s) {
            red[threadIdx.x]  += red[threadIdx.x + s];
            redc[threadIdx.x] += redc[threadIdx.x + s];
        }
        __syncthreads();
    }
    if (threadIdx.x == 0) {
        out[0] = red[0] / (float)NROWS;
        out[1] = (float)redc[0];
    }
}

extern "C" void kernel_launch(void* const* d_in, const int* in_sizes, int n_in,
                              void* d_out, int out_size) {
    const float* X = (const float*)d_in[0];  // [2*BATCH, FEAT] fp32
    const int*   T = (const int*)d_in[1];    // [2*BATCH] int32
    float* out = (float*)d_out;

    prep_kernel<<<NROWS / 8, 256>>>(X);
    dist_kernel<<<dim3(BATCH / BN, BATCH / BM), 256>>>(X, T);
    finalize_kernel<<<1, 256>>>(out);
}

// round 3
// speedup vs baseline: 1.7179x; 1.7179x over previous
#include <cuda_runtime.h>
#include <cuda_bf16.h>
#include <stdint.h>
#include <math.h>

#define BATCH 8192
#define FEAT  128
#define NROWS (2 * BATCH)
#define MARGINF 0.3f

// ---------------- device scratch (no allocations allowed) ----------------
__device__ float g_sq[NROWS];
__device__ int   g_ap_row[BATCH];
__device__ int   g_an_row[BATCH];
__device__ int   g_ap_col[BATCH];
__device__ int   g_an_col[BATCH];
__device__ __nv_bfloat16 g_hi[(size_t)NROWS * FEAT];
__device__ __nv_bfloat16 g_lo[(size_t)NROWS * FEAT];

// ---------------- helpers ----------------
__device__ __forceinline__ uint32_t sm_u32(const void* p) {
    uint32_t a;
    asm("{ .reg .u64 t; cvta.to.shared.u64 t, %1; cvt.u32.u64 %0, t; }"
        : "=r"(a) : "l"(p));
    return a;
}
__device__ __forceinline__ void cp_async16(uint32_t dst, const void* src) {
    asm volatile("cp.async.cg.shared.global [%0], [%1], 16;"
                 :: "r"(dst), "l"(src));
}
__device__ __forceinline__ void ldsm_x4(uint32_t& r0, uint32_t& r1,
                                        uint32_t& r2, uint32_t& r3, uint32_t a) {
    asm volatile("ldmatrix.sync.aligned.m8n8.x4.shared.b16 {%0,%1,%2,%3}, [%4];"
                 : "=r"(r0), "=r"(r1), "=r"(r2), "=r"(r3) : "r"(a));
}
__device__ __forceinline__ void mma_bf16(float* d, const uint32_t* a,
                                         const uint32_t* b) {
    asm volatile(
        "mma.sync.aligned.m16n8k16.row.col.f32.bf16.bf16.f32 "
        "{%0,%1,%2,%3}, {%4,%5,%6,%7}, {%8,%9}, {%0,%1,%2,%3};"
        : "+f"(d[0]), "+f"(d[1]), "+f"(d[2]), "+f"(d[3])
        : "r"(a[0]), "r"(a[1]), "r"(a[2]), "r"(a[3]), "r"(b[0]), "r"(b[1]));
}

// SMEM tile geometry: 128 rows x 32 bf16 per stage, row stride 80B
#define ROW_B   80
#define STAGE_B (128 * ROW_B)   // 10240

// ---------------------------------------------------------------------------
// Kernel A: squared norms + bf16 hi/lo split + mining-array init
// ---------------------------------------------------------------------------
__global__ void prep_kernel(const float* __restrict__ inp) {
    int row  = blockIdx.x * 8 + (threadIdx.x >> 5);
    int lane = threadIdx.x & 31;
    float4 v = reinterpret_cast<const float4*>(inp + (size_t)row * FEAT)[lane];
    float s = v.x * v.x + v.y * v.y + v.z * v.z + v.w * v.w;
#pragma unroll
    for (int o = 16; o; o >>= 1) s += __shfl_down_sync(0xffffffffu, s, o);
    if (lane == 0) g_sq[row] = s;

    float xs[4] = {v.x, v.y, v.z, v.w};
    __nv_bfloat16 h[4], l[4];
#pragma unroll
    for (int i = 0; i < 4; i++) {
        h[i] = __float2bfloat16(xs[i]);
        l[i] = __float2bfloat16(xs[i] - __bfloat162float(h[i]));
    }
    __nv_bfloat162* ph = reinterpret_cast<__nv_bfloat162*>(g_hi + (size_t)row * FEAT);
    __nv_bfloat162* pl = reinterpret_cast<__nv_bfloat162*>(g_lo + (size_t)row * FEAT);
    ph[lane * 2 + 0] = __nv_bfloat162(h[0], h[1]);
    ph[lane * 2 + 1] = __nv_bfloat162(h[2], h[3]);
    pl[lane * 2 + 0] = __nv_bfloat162(l[0], l[1]);
    pl[lane * 2 + 1] = __nv_bfloat162(l[2], l[3]);

    int idx = blockIdx.x * blockDim.x + threadIdx.x;
    if (idx < BATCH) {
        g_ap_row[idx] = 0;
        g_an_row[idx] = 0x7f800000;
        g_ap_col[idx] = 0;
        g_an_col[idx] = 0x7f800000;
    }
}

// ---------------------------------------------------------------------------
// Kernel B: 128x128 distance tile via mma.sync bf16 (hi/lo split, fp32 acc)
// 12 K-iterations of BK=32: pass 0: hi*hi, pass 1: hi*lo, pass 2: lo*hi.
// ---------------------------------------------------------------------------
__global__ __launch_bounds__(256) void dist_mma_kernel(const int* __restrict__ T) {
    __shared__ __align__(16) char s_tiles[4 * STAGE_B];  // A s0,A s1,B s0,B s1
    __shared__ int   s_t0[128], s_t1[128];
    __shared__ float s_sqm[128], s_sqn[128];
    __shared__ int   s_apr[128], s_anr[128], s_apc[128], s_anc[128];

    const int tid  = threadIdx.x;
    const int lane = tid & 31;
    const int warp = tid >> 5;
    const int wm   = warp >> 2;   // 0..1
    const int wn   = warp & 3;    // 0..3
    const int m0   = blockIdx.y * 128;
    const int n0   = blockIdx.x * 128;

    if (tid < 128) {
        s_t0[tid]  = T[m0 + tid];
        s_t1[tid]  = T[BATCH + n0 + tid];
        s_sqm[tid] = g_sq[m0 + tid];
        s_sqn[tid] = g_sq[BATCH + n0 + tid];
        s_apr[tid] = 0;
        s_anr[tid] = 0x7f800000;
        s_apc[tid] = 0;
        s_anc[tid] = 0x7f800000;
    }

    const uint32_t smA = sm_u32(s_tiles);
    const uint32_t smB = smA + 2 * STAGE_B;

    // cp.async assignment: 512 16B-chunks per matrix per iter; 2 per thread
    const int ld_r0 = tid >> 2;          // rows tid/4 and tid/4+64
    const int ld_c  = tid & 3;           // 16B chunk within 64B K-slab
    const uint32_t dA0 = smA + ld_r0 * ROW_B + ld_c * 16;
    const uint32_t dA1 = smA + (ld_r0 + 64) * ROW_B + ld_c * 16;
    const uint32_t dB0 = smB + ld_r0 * ROW_B + ld_c * 16;
    const uint32_t dB1 = smB + (ld_r0 + 64) * ROW_B + ld_c * 16;

    // ldmatrix lane address patterns
    const int a_row = wm * 64 + (lane & 15);
    const int a_kh  = lane >> 4;
    const uint32_t aA = smA + a_row * ROW_B + a_kh * 16;
    const int bq = lane >> 3;
    const int b_c = bq & 1;
    uint32_t aB[2];
#pragma unroll
    for (int j = 0; j < 2; j++) {
        int n_row = wn * 32 + (2 * j + (bq >> 1)) * 8 + (lane & 7);
        aB[j] = smB + n_row * ROW_B + b_c * 16;
    }

    float acc[4][4][4];
#pragma unroll
    for (int mi = 0; mi < 4; mi++)
#pragma unroll
        for (int ni = 0; ni < 4; ni++)
#pragma unroll
            for (int e = 0; e < 4; e++) acc[mi][ni][e] = 0.f;

    // ---- issue iteration 0 ----
    {
        const __nv_bfloat16* Asrc = g_hi + (size_t)m0 * FEAT;
        const __nv_bfloat16* Bsrc = g_hi + (size_t)(BATCH + n0) * FEAT;
        cp_async16(dA0, Asrc + (size_t)ld_r0 * FEAT + ld_c * 8);
        cp_async16(dA1, Asrc + (size_t)(ld_r0 + 64) * FEAT + ld_c * 8);
        cp_async16(dB0, Bsrc + (size_t)ld_r0 * FEAT + ld_c * 8);
        cp_async16(dB1, Bsrc + (size_t)(ld_r0 + 64) * FEAT + ld_c * 8);
        asm volatile("cp.async.commit_group;");
    }

#pragma unroll
    for (int it = 0; it < 12; it++) {
        if (it < 11) {
            const int it2   = it + 1;
            const int pass  = it2 >> 2;
            const int kk    = (it2 & 3) * 32;
            const __nv_bfloat16* Asrc =
                ((pass < 2) ? g_hi : g_lo) + (size_t)m0 * FEAT + kk;
            const __nv_bfloat16* Bsrc =
                ((pass == 1) ? g_lo : g_hi) + (size_t)(BATCH + n0) * FEAT + kk;
            const uint32_t so = (it2 & 1) * STAGE_B;
            cp_async16(dA0 + so, Asrc + (size_t)ld_r0 * FEAT + ld_c * 8);
            cp_async16(dA1 + so, Asrc + (size_t)(ld_r0 + 64) * FEAT + ld_c * 8);
            cp_async16(dB0 + so, Bsrc + (size_t)ld_r0 * FEAT + ld_c * 8);
            cp_async16(dB1 + so, Bsrc + (size_t)(ld_r0 + 64) * FEAT + ld_c * 8);
            asm volatile("cp.async.commit_group;");
            asm volatile("cp.async.wait_group 1;");
        } else {
            asm volatile("cp.async.wait_group 0;");
        }
        __syncthreads();

        const uint32_t so = (it & 1) * STAGE_B;
#pragma unroll
        for (int ks = 0; ks < 2; ks++) {
            uint32_t a[4][4], b[4][2];
#pragma unroll
            for (int mi = 0; mi < 4; mi++)
                ldsm_x4(a[mi][0], a[mi][1], a[mi][2], a[mi][3],
                        aA + so + mi * (16 * ROW_B) + ks * 32);
#pragma unroll
            for (int j = 0; j < 2; j++) {
                uint32_t r0, r1, r2, r3;
                ldsm_x4(r0, r1, r2, r3, aB[j] + so + ks * 32);
                b[2 * j + 0][0] = r0;  b[2 * j + 0][1] = r1;
                b[2 * j + 1][0] = r2;  b[2 * j + 1][1] = r3;
            }
#pragma unroll
            for (int mi = 0; mi < 4; mi++)
#pragma unroll
                for (int ni = 0; ni < 4; ni++)
                    mma_bf16(acc[mi][ni], a[mi], b[ni]);
        }
        __syncthreads();   // compute done before next iter overwrites its stage
    }

    // ---- epilogue: d2 + masked mining on register fragments ----
    // thread owns rows  m_loc = wm*64 + mi*16 + (lane>>2) + 8*h   (mi,h)
    //            cols  n_loc = wn*32 + ni*8  + 2*(lane&3) + e     (ni,e)
    float sqm_r[8], sqn_r[8];
    int   tm_r[8], tn_r[8];
#pragma unroll
    for (int mi = 0; mi < 4; mi++)
#pragma unroll
        for (int h = 0; h < 2; h++) {
            int m_loc = wm * 64 + mi * 16 + (lane >> 2) + 8 * h;
            sqm_r[mi * 2 + h] = s_sqm[m_loc];
            tm_r[mi * 2 + h]  = s_t0[m_loc];
        }
#pragma unroll
    for (int ni = 0; ni < 4; ni++)
#pragma unroll
        for (int e = 0; e < 2; e++) {
            int n_loc = wn * 32 + ni * 8 + 2 * (lane & 3) + e;
            sqn_r[ni * 2 + e] = s_sqn[n_loc];
            tn_r[ni * 2 + e]  = s_t1[n_loc];
        }

    float apr[8], anr[8], apc[8], anc[8];
#pragma unroll
    for (int i = 0; i < 8; i++) {
        apr[i] = 0.f;  anr[i] = __int_as_float(0x7f800000);
        apc[i] = 0.f;  anc[i] = __int_as_float(0x7f800000);
    }

#pragma unroll
    for (int mi = 0; mi < 4; mi++)
#pragma unroll
        for (int ni = 0; ni < 4; ni++)
#pragma unroll
            for (int h = 0; h < 2; h++)
#pragma unroll
                for (int e = 0; e < 2; e++) {
                    int ri = mi * 2 + h, ci = ni * 2 + e;
                    float dot = acc[mi][ni][h * 2 + e];
                    float d2 = fmaxf(fmaf(-2.f, dot, sqm_r[ri] + sqn_r[ci]), 0.f);
                    if (tm_r[ri] == tn_r[ci]) {
                        apr[ri] = fmaxf(apr[ri], d2);
                        apc[ci] = fmaxf(apc[ci], d2);
                    } else {
                        anr[ri] = fminf(anr[ri], d2);
                        anc[ci] = fminf(anc[ci], d2);
                    }
                }

#pragma unroll
    for (int mi = 0; mi < 4; mi++)
#pragma unroll
        for (int h = 0; h < 2; h++) {
            int m_loc = wm * 64 + mi * 16 + (lane >> 2) + 8 * h;
            atomicMax(&s_apr[m_loc], __float_as_int(apr[mi * 2 + h]));
            atomicMin(&s_anr[m_loc], __float_as_int(anr[mi * 2 + h]));
        }
#pragma unroll
    for (int ni = 0; ni < 4; ni++)
#pragma unroll
        for (int e = 0; e < 2; e++) {
            int n_loc = wn * 32 + ni * 8 + 2 * (lane & 3) + e;
            atomicMax(&s_apc[n_loc], __float_as_int(apc[ni * 2 + e]));
            atomicMin(&s_anc[n_loc], __float_as_int(anc[ni * 2 + e]));
        }
    __syncthreads();

    if (tid < 128) {
        if (s_apr[tid] != 0)          atomicMax(&g_ap_row[m0 + tid], s_apr[tid]);
        if (s_anr[tid] != 0x7f800000) atomicMin(&g_an_row[m0 + tid], s_anr[tid]);
        if (s_apc[tid] != 0)          atomicMax(&g_ap_col[n0 + tid], s_apc[tid]);
        if (s_anc[tid] != 0x7f800000) atomicMin(&g_an_col[n0 + tid], s_anc[tid]);
    }
}

// ---------------------------------------------------------------------------
// Kernel C: final loss / correct reduction
// ---------------------------------------------------------------------------
__global__ void finalize_kernel(float* __restrict__ out) {
    __shared__ float red[256];
    __shared__ int   redc[256];
    float lsum = 0.f;
    int   cnt  = 0;
    for (int i = threadIdx.x; i < NROWS; i += 256) {
        float apd2, and2;
        if (i < BATCH) {
            apd2 = __int_as_float(g_ap_row[i]);
            and2 = __int_as_float(g_an_row[i]);
        } else {
            apd2 = __int_as_float(g_ap_col[i - BATCH]);
            and2 = __int_as_float(g_an_col[i - BATCH]);
        }
        float ap = sqrtf(fmaxf(apd2, 1e-12f));
        float an = sqrtf(fmaxf(and2, 1e-12f));
        lsum += fmaxf(ap - an + MARGINF, 0.f);
        cnt  += (an >= ap) ? 1 : 0;
    }
    red[threadIdx.x]  = lsum;
    redc[threadIdx.x] = cnt;
    __syncthreads();
    for (int s = 128; s; s >>= 1) {
        if (threadIdx.x < s) {
            red[threadIdx.x]  += red[threadIdx.x + s];
            redc[threadIdx.x] += redc[threadIdx.x + s];
        }
        __syncthreads();
    }
    if (threadIdx.x == 0) {
        out[0] = red[0] / (float)NROWS;
        out[1] = (float)redc[0];
    }
}

extern "C" void kernel_launch(void* const* d_in, const int* in_sizes, int n_in,
                              void* d_out, int out_size) {
    const float* X = (const float*)d_in[0];
    const int*   T = (const int*)d_in[1];
    float* out = (float*)d_out;

    prep_kernel<<<NROWS / 8, 256>>>(X);
    dist_mma_kernel<<<dim3(BATCH / 128, BATCH / 128), 256>>>(T);
    finalize_kernel<<<1, 256>>>(out);
}

// round 4
// speedup vs baseline: 2.2030x; 1.2824x over previous
#include <cuda_runtime.h>
#include <cuda_bf16.h>
#include <stdint.h>
#include <math.h>

#define BATCH 8192
#define FEAT  128
#define NROWS (2 * BATCH)
#define MARGINF 0.3f

// ---------------- device scratch ----------------
__device__ float g_sq[NROWS];
__device__ int   g_ap_row[BATCH];
__device__ int   g_an_row[BATCH];
__device__ int   g_ap_col[BATCH];
__device__ int   g_an_col[BATCH];
__device__ __nv_bfloat16 g_hi[(size_t)NROWS * FEAT];
__device__ __nv_bfloat16 g_lo[(size_t)NROWS * FEAT];

// ---------------- helpers ----------------
__device__ __forceinline__ uint32_t sm_u32(const void* p) {
    uint32_t a;
    asm("{ .reg .u64 t; cvta.to.shared.u64 t, %1; cvt.u32.u64 %0, t; }"
        : "=r"(a) : "l"(p));
    return a;
}
__device__ __forceinline__ void cp_async16(uint32_t dst, const void* src) {
    asm volatile("cp.async.cg.shared.global [%0], [%1], 16;"
                 :: "r"(dst), "l"(src));
}
__device__ __forceinline__ void ldsm_x4(uint32_t& r0, uint32_t& r1,
                                        uint32_t& r2, uint32_t& r3, uint32_t a) {
    asm volatile("ldmatrix.sync.aligned.m8n8.x4.shared.b16 {%0,%1,%2,%3}, [%4];"
                 : "=r"(r0), "=r"(r1), "=r"(r2), "=r"(r3) : "r"(a));
}
__device__ __forceinline__ void mma_bf16(float* d, const uint32_t* a,
                                         const uint32_t* b) {
    asm volatile(
        "mma.sync.aligned.m16n8k16.row.col.f32.bf16.bf16.f32 "
        "{%0,%1,%2,%3}, {%4,%5,%6,%7}, {%8,%9}, {%0,%1,%2,%3};"
        : "+f"(d[0]), "+f"(d[1]), "+f"(d[2]), "+f"(d[3])
        : "r"(a[0]), "r"(a[1]), "r"(a[2]), "r"(a[3]), "r"(b[0]), "r"(b[1]));
}

// SMEM tile geometry: per stage 128 rows x 32 bf16, row stride 80B (conflict-free LDSM)
#define ROW_B    80
#define STAGE_B  (128 * ROW_B)      // 10240
#define NSTAGE   4
#define OFF_A    0                   // 4 stages: 40960
#define OFF_B    (NSTAGE * STAGE_B)  // 40960, 4 stages: 40960
#define OFF_MISC (2 * NSTAGE * STAGE_B)  // 81920
// misc: t0[128] t1[128] sqm[128] sqn[128] apr[128] anr[128] apc[128] anc[128]
#define SMEM_TOTAL (OFF_MISC + 8 * 128 * 4)   // 86016

// ---------------------------------------------------------------------------
// Kernel A: squared norms + bf16 hi/lo split + mining-array init
// ---------------------------------------------------------------------------
__global__ void prep_kernel(const float* __restrict__ inp) {
    int row  = blockIdx.x * 8 + (threadIdx.x >> 5);
    int lane = threadIdx.x & 31;
    float4 v = reinterpret_cast<const float4*>(inp + (size_t)row * FEAT)[lane];
    float s = v.x * v.x + v.y * v.y + v.z * v.z + v.w * v.w;
#pragma unroll
    for (int o = 16; o; o >>= 1) s += __shfl_down_sync(0xffffffffu, s, o);
    if (lane == 0) g_sq[row] = s;

    float xs[4] = {v.x, v.y, v.z, v.w};
    __nv_bfloat16 h[4], l[4];
#pragma unroll
    for (int i = 0; i < 4; i++) {
        h[i] = __float2bfloat16(xs[i]);
        l[i] = __float2bfloat16(xs[i] - __bfloat162float(h[i]));
    }
    __nv_bfloat162* ph = reinterpret_cast<__nv_bfloat162*>(g_hi + (size_t)row * FEAT);
    __nv_bfloat162* pl = reinterpret_cast<__nv_bfloat162*>(g_lo + (size_t)row * FEAT);
    ph[lane * 2 + 0] = __nv_bfloat162(h[0], h[1]);
    ph[lane * 2 + 1] = __nv_bfloat162(h[2], h[3]);
    pl[lane * 2 + 0] = __nv_bfloat162(l[0], l[1]);
    pl[lane * 2 + 1] = __nv_bfloat162(l[2], l[3]);

    int idx = blockIdx.x * blockDim.x + threadIdx.x;
    if (idx < BATCH) {
        g_ap_row[idx] = 0;
        g_an_row[idx] = 0x7f800000;
        g_ap_col[idx] = 0;
        g_an_col[idx] = 0x7f800000;
    }
}

// ---------------------------------------------------------------------------
// Kernel B: 128x128 distance tile via mma.sync bf16, 4-stage cp.async pipeline
// 12 K-iterations of BK=32: pass 0 hi*hi, pass 1 hi*lo, pass 2 lo*hi.
// ---------------------------------------------------------------------------
__global__ __launch_bounds__(256, 2) void dist_mma_kernel(const int* __restrict__ T) {
    extern __shared__ __align__(16) char sm[];
    int*   s_t0  = reinterpret_cast<int*>(sm + OFF_MISC);
    int*   s_t1  = reinterpret_cast<int*>(sm + OFF_MISC + 512);
    float* s_sqm = reinterpret_cast<float*>(sm + OFF_MISC + 1024);
    float* s_sqn = reinterpret_cast<float*>(sm + OFF_MISC + 1536);
    int*   s_apr = reinterpret_cast<int*>(sm + OFF_MISC + 2048);
    int*   s_anr = reinterpret_cast<int*>(sm + OFF_MISC + 2560);
    int*   s_apc = reinterpret_cast<int*>(sm + OFF_MISC + 3072);
    int*   s_anc = reinterpret_cast<int*>(sm + OFF_MISC + 3584);

    const int tid  = threadIdx.x;
    const int lane = tid & 31;
    const int warp = tid >> 5;
    const int wm   = warp >> 2;   // 0..1
    const int wn   = warp & 3;    // 0..3
    const int m0   = blockIdx.y * 128;
    const int n0   = blockIdx.x * 128;

    if (tid < 128) {
        s_t0[tid]  = T[m0 + tid];
        s_t1[tid]  = T[BATCH + n0 + tid];
        s_sqm[tid] = g_sq[m0 + tid];
        s_sqn[tid] = g_sq[BATCH + n0 + tid];
        s_apr[tid] = 0;
        s_anr[tid] = 0x7f800000;
        s_apc[tid] = 0;
        s_anc[tid] = 0x7f800000;
    }

    const uint32_t smA = sm_u32(sm) + OFF_A;
    const uint32_t smB = sm_u32(sm) + OFF_B;

    // cp.async: 2 rows per matrix per thread (rows tid/4 and tid/4+64)
    const int ld_r0 = tid >> 2;
    const int ld_c  = tid & 3;
    const uint32_t dA0 = smA + ld_r0 * ROW_B + ld_c * 16;
    const uint32_t dA1 = smA + (ld_r0 + 64) * ROW_B + ld_c * 16;
    const uint32_t dB0 = smB + ld_r0 * ROW_B + ld_c * 16;
    const uint32_t dB1 = smB + (ld_r0 + 64) * ROW_B + ld_c * 16;
    const size_t gA0 = (size_t)ld_r0 * FEAT + ld_c * 8;
    const size_t gA1 = (size_t)(ld_r0 + 64) * FEAT + ld_c * 8;

    // ldmatrix lane address patterns (same as validated R3 mapping)
    const int a_row = wm * 64 + (lane & 15);
    const int a_kh  = lane >> 4;
    const uint32_t aA = smA + a_row * ROW_B + a_kh * 16;
    const int bq  = lane >> 3;
    const int b_c = bq & 1;
    uint32_t aB[2];
#pragma unroll
    for (int j = 0; j < 2; j++) {
        int n_row = wn * 32 + (2 * j + (bq >> 1)) * 8 + (lane & 7);
        aB[j] = smB + n_row * ROW_B + b_c * 16;
    }

    float acc[4][4][4];
#pragma unroll
    for (int mi = 0; mi < 4; mi++)
#pragma unroll
        for (int ni = 0; ni < 4; ni++)
#pragma unroll
            for (int e = 0; e < 4; e++) acc[mi][ni][e] = 0.f;

    const __nv_bfloat16* baseA = g_hi + (size_t)m0 * FEAT;           // pass 0,1 A
    const __nv_bfloat16* baseAl = g_lo + (size_t)m0 * FEAT;          // pass 2 A
    const __nv_bfloat16* baseBh = g_hi + (size_t)(BATCH + n0) * FEAT;
    const __nv_bfloat16* baseBl = g_lo + (size_t)(BATCH + n0) * FEAT;

    // issue loads for iteration `it` into stage `it % NSTAGE`
    auto issue = [&](int it) {
        const int pass = it >> 2;
        const int kk   = (it & 3) * 32;
        const __nv_bfloat16* As = ((pass < 2) ? baseA : baseAl) + kk;
        const __nv_bfloat16* Bs = ((pass == 1) ? baseBl : baseBh) + kk;
        const uint32_t so = (uint32_t)(it & (NSTAGE - 1)) * STAGE_B;
        cp_async16(dA0 + so, As + gA0);
        cp_async16(dA1 + so, As + gA1);
        cp_async16(dB0 + so, Bs + gA0);
        cp_async16(dB1 + so, Bs + gA1);
    };

    // preload stages 0..2 (groups 0..2)
#pragma unroll
    for (int p = 0; p < NSTAGE - 1; p++) {
        issue(p);
        asm volatile("cp.async.commit_group;");
    }

#pragma unroll
    for (int it = 0; it < 12; it++) {
        // guarantee group `it` (stage it%4) complete: all but 2 newest groups done
        asm volatile("cp.async.wait_group 2;");
        __syncthreads();   // also: everyone done consuming stage (it-1)%4 last iter

        if (it + NSTAGE - 1 < 12) issue(it + NSTAGE - 1);
        asm volatile("cp.async.commit_group;");   // empty groups keep count aligned

        const uint32_t so = (uint32_t)(it & (NSTAGE - 1)) * STAGE_B;
#pragma unroll
        for (int ks = 0; ks < 2; ks++) {
            uint32_t a[4][4], b[4][2];
#pragma unroll
            for (int mi = 0; mi < 4; mi++)
                ldsm_x4(a[mi][0], a[mi][1], a[mi][2], a[mi][3],
                        aA + so + mi * (16 * ROW_B) + ks * 32);
#pragma unroll
            for (int j = 0; j < 2; j++) {
                uint32_t r0, r1, r2, r3;
                ldsm_x4(r0, r1, r2, r3, aB[j] + so + ks * 32);
                b[2 * j + 0][0] = r0;  b[2 * j + 0][1] = r1;
                b[2 * j + 1][0] = r2;  b[2 * j + 1][1] = r3;
            }
#pragma unroll
            for (int mi = 0; mi < 4; mi++)
#pragma unroll
                for (int ni = 0; ni < 4; ni++)
                    mma_bf16(acc[mi][ni], a[mi], b[ni]);
        }
    }

    // ---- epilogue: d2 + masked mining on register fragments ----
    float sqm_r[8], sqn_r[8];
    int   tm_r[8], tn_r[8];
#pragma unroll
    for (int mi = 0; mi < 4; mi++)
#pragma unroll
        for (int h = 0; h < 2; h++) {
            int m_loc = wm * 64 + mi * 16 + (lane >> 2) + 8 * h;
            sqm_r[mi * 2 + h] = s_sqm[m_loc];
            tm_r[mi * 2 + h]  = s_t0[m_loc];
        }
#pragma unroll
    for (int ni = 0; ni < 4; ni++)
#pragma unroll
        for (int e = 0; e < 2; e++) {
            int n_loc = wn * 32 + ni * 8 + 2 * (lane & 3) + e;
            sqn_r[ni * 2 + e] = s_sqn[n_loc];
            tn_r[ni * 2 + e]  = s_t1[n_loc];
        }

    float apr[8], anr[8], apc[8], anc[8];
#pragma unroll
    for (int i = 0; i < 8; i++) {
        apr[i] = 0.f;  anr[i] = __int_as_float(0x7f800000);
        apc[i] = 0.f;  anc[i] = __int_as_float(0x7f800000);
    }

#pragma unroll
    for (int mi = 0; mi < 4; mi++)
#pragma unroll
        for (int ni = 0; ni < 4; ni++)
#pragma unroll
            for (int h = 0; h < 2; h++)
#pragma unroll
                for (int e = 0; e < 2; e++) {
                    int ri = mi * 2 + h, ci = ni * 2 + e;
                    float dot = acc[mi][ni][h * 2 + e];
                    float d2 = fmaxf(fmaf(-2.f, dot, sqm_r[ri] + sqn_r[ci]), 0.f);
                    if (tm_r[ri] == tn_r[ci]) {
                        apr[ri] = fmaxf(apr[ri], d2);
                        apc[ci] = fmaxf(apc[ci], d2);
                    } else {
                        anr[ri] = fminf(anr[ri], d2);
                        anc[ci] = fminf(anc[ci], d2);
                    }
                }

#pragma unroll
    for (int mi = 0; mi < 4; mi++)
#pragma unroll
        for (int h = 0; h < 2; h++) {
            int m_loc = wm * 64 + mi * 16 + (lane >> 2) + 8 * h;
            atomicMax(&s_apr[m_loc], __float_as_int(apr[mi * 2 + h]));
            atomicMin(&s_anr[m_loc], __float_as_int(anr[mi * 2 + h]));
        }
#pragma unroll
    for (int ni = 0; ni < 4; ni++)
#pragma unroll
        for (int e = 0; e < 2; e++) {
            int n_loc = wn * 32 + ni * 8 + 2 * (lane & 3) + e;
            atomicMax(&s_apc[n_loc], __float_as_int(apc[ni * 2 + e]));
            atomicMin(&s_anc[n_loc], __float_as_int(anc[ni * 2 + e]));
        }
    __syncthreads();

    if (tid < 128) {
        if (s_apr[tid] != 0)          atomicMax(&g_ap_row[m0 + tid], s_apr[tid]);
        if (s_anr[tid] != 0x7f800000) atomicMin(&g_an_row[m0 + tid], s_anr[tid]);
        if (s_apc[tid] != 0)          atomicMax(&g_ap_col[n0 + tid], s_apc[tid]);
        if (s_anc[tid] != 0x7f800000) atomicMin(&g_an_col[n0 + tid], s_anc[tid]);
    }
}

// ---------------------------------------------------------------------------
// Kernel C: final loss / correct reduction
// ---------------------------------------------------------------------------
__global__ void finalize_kernel(float* __restrict__ out) {
    __shared__ float red[256];
    __shared__ int   redc[256];
    float lsum = 0.f;
    int   cnt  = 0;
    for (int i = threadIdx.x; i < NROWS; i += 256) {
        float apd2, and2;
        if (i < BATCH) {
            apd2 = __int_as_float(g_ap_row[i]);
            and2 = __int_as_float(g_an_row[i]);
        } else {
            apd2 = __int_as_float(g_ap_col[i - BATCH]);
            and2 = __int_as_float(g_an_col[i - BATCH]);
        }
        float ap = sqrtf(fmaxf(apd2, 1e-12f));
        float an = sqrtf(fmaxf(and2, 1e-12f));
        lsum += fmaxf(ap - an + MARGINF, 0.f);
        cnt  += (an >= ap) ? 1 : 0;
    }
    red[threadIdx.x]  = lsum;
    redc[threadIdx.x] = cnt;
    __syncthreads();
    for (int s = 128; s; s >>= 1) {
        if (threadIdx.x < s) {
            red[threadIdx.x]  += red[threadIdx.x + s];
            redc[threadIdx.x] += redc[threadIdx.x + s];
        }
        __syncthreads();
    }
    if (threadIdx.x == 0) {
        out[0] = red[0] / (float)NROWS;
        out[1] = (float)redc[0];
    }
}

extern "C" void kernel_launch(void* const* d_in, const int* in_sizes, int n_in,
                              void* d_out, int out_size) {
    const float* X = (const float*)d_in[0];
    const int*   T = (const int*)d_in[1];
    float* out = (float*)d_out;

    static bool attr_set = false;
    if (!attr_set) {
        cudaFuncSetAttribute(dist_mma_kernel,
                             cudaFuncAttributeMaxDynamicSharedMemorySize, SMEM_TOTAL);
        attr_set = true;
    }

    prep_kernel<<<NROWS / 8, 256>>>(X);
    dist_mma_kernel<<<dim3(BATCH / 128, BATCH / 128), 256, SMEM_TOTAL>>>(T);
    finalize_kernel<<<1, 256>>>(out);
}

// round 5
// speedup vs baseline: 2.3873x; 1.0837x over previous
#include <cuda_runtime.h>
#include <cuda_bf16.h>
#include <stdint.h>
#include <math.h>

#define BATCH 8192
#define FEAT  128
#define NROWS (2 * BATCH)
#define MARGINF 0.3f
#define NUM_IDS 1000
#define LISTCAP 64
#define W_D2 1.0f     // refine window on approx d2 (err bound ~0.11 @5sigma)

typedef unsigned long long u64;

// ---------------- device scratch ----------------
__device__ float g_sq[NROWS];
__device__ __nv_bfloat16 g_hi[(size_t)NROWS * FEAT];
__device__ u64  g_rowmin[BATCH][64];   // per (mod0-row, col-block): packed (d2,partner)
__device__ u64  g_colmin[BATCH][64];   // per (mod1-row, row-block)
__device__ int  g_cnt[2][NUM_IDS];
__device__ int  g_list[2][NUM_IDS][LISTCAP];
__device__ float g_apf[NROWS];
__device__ float g_anf[NROWS];

// ---------------- helpers ----------------
__device__ __forceinline__ uint32_t sm_u32(const void* p) {
    uint32_t a;
    asm("{ .reg .u64 t; cvta.to.shared.u64 t, %1; cvt.u32.u64 %0, t; }"
        : "=r"(a) : "l"(p));
    return a;
}
__device__ __forceinline__ void cp_async16(uint32_t dst, const void* src) {
    asm volatile("cp.async.cg.shared.global [%0], [%1], 16;"
                 :: "r"(dst), "l"(src));
}
__device__ __forceinline__ void ldsm_x4(uint32_t& r0, uint32_t& r1,
                                        uint32_t& r2, uint32_t& r3, uint32_t a) {
    asm volatile("ldmatrix.sync.aligned.m8n8.x4.shared.b16 {%0,%1,%2,%3}, [%4];"
                 : "=r"(r0), "=r"(r1), "=r"(r2), "=r"(r3) : "r"(a));
}
__device__ __forceinline__ void mma_bf16(float* d, const uint32_t* a,
                                         const uint32_t* b) {
    asm volatile(
        "mma.sync.aligned.m16n8k16.row.col.f32.bf16.bf16.f32 "
        "{%0,%1,%2,%3}, {%4,%5,%6,%7}, {%8,%9}, {%0,%1,%2,%3};"
        : "+f"(d[0]), "+f"(d[1]), "+f"(d[2]), "+f"(d[3])
        : "r"(a[0]), "r"(a[1]), "r"(a[2]), "r"(a[3]), "r"(b[0]), "r"(b[1]));
}

// SMEM tile geometry: 128 rows x 32 bf16 per stage, stride 80B (conflict-free)
#define ROW_B    80
#define STAGE_B  (128 * ROW_B)       // 10240
#define NSTAGE   4
#define OFF_A    0
#define OFF_B    (NSTAGE * STAGE_B)  // 40960
#define OFF_MISC (2 * NSTAGE * STAGE_B)  // 81920
// misc: t0[128] t1[128] sqm[128] sqn[128] rowmin u64[128] colmin u64[128]
#define SMEM_TOTAL (OFF_MISC + 512 + 512 + 512 + 512 + 1024 + 1024)  // 86016

// ---------------------------------------------------------------------------
// Kernel A: squared norms + bf16 hi + zero label counters
// ---------------------------------------------------------------------------
__global__ void prep_kernel(const float* __restrict__ inp) {
    int row  = blockIdx.x * 8 + (threadIdx.x >> 5);
    int lane = threadIdx.x & 31;
    float4 v = reinterpret_cast<const float4*>(inp + (size_t)row * FEAT)[lane];
    float s = v.x * v.x + v.y * v.y + v.z * v.z + v.w * v.w;
#pragma unroll
    for (int o = 16; o; o >>= 1) s += __shfl_down_sync(0xffffffffu, s, o);
    if (lane == 0) g_sq[row] = s;

    __nv_bfloat162* ph = reinterpret_cast<__nv_bfloat162*>(g_hi + (size_t)row * FEAT);
    ph[lane * 2 + 0] = __nv_bfloat162(__float2bfloat16(v.x), __float2bfloat16(v.y));
    ph[lane * 2 + 1] = __nv_bfloat162(__float2bfloat16(v.z), __float2bfloat16(v.w));

    int idx = blockIdx.x * blockDim.x + threadIdx.x;
    if (idx < 2 * NUM_IDS) reinterpret_cast<int*>(g_cnt)[idx] = 0;
}

// ---------------------------------------------------------------------------
// Kernel A2: per-label cross-modal index lists
// ---------------------------------------------------------------------------
__global__ void list_kernel(const int* __restrict__ T) {
    int i = blockIdx.x * blockDim.x + threadIdx.x;
    if (i >= NROWS) return;
    int t = T[i];
    int mod = (i >= BATCH) ? 1 : 0;
    int slot = atomicAdd(&g_cnt[mod][t], 1);
    if (slot < LISTCAP) g_list[mod][t][slot] = i;
}

// ---------------------------------------------------------------------------
// Kernel B: 1-pass bf16 approx distance GEMM + negatives-argmin per block
// ---------------------------------------------------------------------------
__global__ __launch_bounds__(256, 2) void dist1_kernel(const int* __restrict__ T) {
    extern __shared__ __align__(16) char sm[];
    int*   s_t0   = reinterpret_cast<int*>(sm + OFF_MISC);
    int*   s_t1   = reinterpret_cast<int*>(sm + OFF_MISC + 512);
    float* s_sqm  = reinterpret_cast<float*>(sm + OFF_MISC + 1024);
    float* s_sqn  = reinterpret_cast<float*>(sm + OFF_MISC + 1536);
    u64*   s_rmin = reinterpret_cast<u64*>(sm + OFF_MISC + 2048);
    u64*   s_cmin = reinterpret_cast<u64*>(sm + OFF_MISC + 3072);

    const int tid  = threadIdx.x;
    const int lane = tid & 31;
    const int warp = tid >> 5;
    const int wm   = warp >> 2;
    const int wn   = warp & 3;
    const int m0   = blockIdx.y * 128;
    const int n0   = blockIdx.x * 128;

    if (tid < 128) {
        s_t0[tid]  = T[m0 + tid];
        s_t1[tid]  = T[BATCH + n0 + tid];
        s_sqm[tid] = g_sq[m0 + tid];
        s_sqn[tid] = g_sq[BATCH + n0 + tid];
        s_rmin[tid] = ~0ull;
        s_cmin[tid] = ~0ull;
    }

    const uint32_t smA = sm_u32(sm) + OFF_A;
    const uint32_t smB = sm_u32(sm) + OFF_B;

    const int ld_r0 = tid >> 2;
    const int ld_c  = tid & 3;
    const uint32_t dA0 = smA + ld_r0 * ROW_B + ld_c * 16;
    const uint32_t dA1 = smA + (ld_r0 + 64) * ROW_B + ld_c * 16;
    const uint32_t dB0 = smB + ld_r0 * ROW_B + ld_c * 16;
    const uint32_t dB1 = smB + (ld_r0 + 64) * ROW_B + ld_c * 16;
    const size_t gA0 = (size_t)ld_r0 * FEAT + ld_c * 8;
    const size_t gA1 = (size_t)(ld_r0 + 64) * FEAT + ld_c * 8;

    const int a_row = wm * 64 + (lane & 15);
    const int a_kh  = lane >> 4;
    const uint32_t aA = smA + a_row * ROW_B + a_kh * 16;
    const int bq  = lane >> 3;
    const int b_c = bq & 1;
    uint32_t aB[2];
#pragma unroll
    for (int j = 0; j < 2; j++) {
        int n_row = wn * 32 + (2 * j + (bq >> 1)) * 8 + (lane & 7);
        aB[j] = smB + n_row * ROW_B + b_c * 16;
    }

    float acc[4][4][4];
#pragma unroll
    for (int mi = 0; mi < 4; mi++)
#pragma unroll
        for (int ni = 0; ni < 4; ni++)
#pragma unroll
            for (int e = 0; e < 4; e++) acc[mi][ni][e] = 0.f;

    const __nv_bfloat16* baseA = g_hi + (size_t)m0 * FEAT;
    const __nv_bfloat16* baseB = g_hi + (size_t)(BATCH + n0) * FEAT;

    // preload all 4 K-slabs (K = 128 = 4 x 32)
#pragma unroll
    for (int p = 0; p < 4; p++) {
        const uint32_t so = (uint32_t)p * STAGE_B;
        const __nv_bfloat16* As = baseA + p * 32;
        const __nv_bfloat16* Bs = baseB + p * 32;
        cp_async16(dA0 + so, As + gA0);
        cp_async16(dA1 + so, As + gA1);
        cp_async16(dB0 + so, Bs + gA0);
        cp_async16(dB1 + so, Bs + gA1);
        asm volatile("cp.async.commit_group;");
    }

#define COMPUTE_STAGE(IT)                                                     \
    do {                                                                      \
        const uint32_t so = (uint32_t)(IT) * STAGE_B;                         \
        _Pragma("unroll")                                                     \
        for (int ks = 0; ks < 2; ks++) {                                      \
            uint32_t a[4][4], b[4][2];                                        \
            _Pragma("unroll")                                                 \
            for (int mi = 0; mi < 4; mi++)                                    \
                ldsm_x4(a[mi][0], a[mi][1], a[mi][2], a[mi][3],               \
                        aA + so + mi * (16 * ROW_B) + ks * 32);               \
            _Pragma("unroll")                                                 \
            for (int j = 0; j < 2; j++) {                                     \
                uint32_t r0, r1, r2, r3;                                      \
                ldsm_x4(r0, r1, r2, r3, aB[j] + so + ks * 32);                \
                b[2 * j + 0][0] = r0;  b[2 * j + 0][1] = r1;                  \
                b[2 * j + 1][0] = r2;  b[2 * j + 1][1] = r3;                  \
            }                                                                 \
            _Pragma("unroll")                                                 \
            for (int mi = 0; mi < 4; mi++)                                    \
                _Pragma("unroll")                                             \
                for (int ni = 0; ni < 4; ni++)                                \
                    mma_bf16(acc[mi][ni], a[mi], b[ni]);                      \
        }                                                                     \
    } while (0)

    asm volatile("cp.async.wait_group 3;");
    __syncthreads();
    COMPUTE_STAGE(0);
    asm volatile("cp.async.wait_group 2;");
    __syncthreads();
    COMPUTE_STAGE(1);
    asm volatile("cp.async.wait_group 1;");
    __syncthreads();
    COMPUTE_STAGE(2);
    asm volatile("cp.async.wait_group 0;");
    __syncthreads();
    COMPUTE_STAGE(3);
#undef COMPUTE_STAGE

    // ---- epilogue: approx d2 + negatives argmin (packed u64) ----
    int m_loc[8], n_loc[8];
    float sqm_r[8], sqn_r[8];
    int   tm_r[8], tn_r[8];
#pragma unroll
    for (int mi = 0; mi < 4; mi++)
#pragma unroll
        for (int h = 0; h < 2; h++) {
            int ml = wm * 64 + mi * 16 + (lane >> 2) + 8 * h;
            m_loc[mi * 2 + h] = ml;
            sqm_r[mi * 2 + h] = s_sqm[ml];
            tm_r[mi * 2 + h]  = s_t0[ml];
        }
#pragma unroll
    for (int ni = 0; ni < 4; ni++)
#pragma unroll
        for (int e = 0; e < 2; e++) {
            int nl = wn * 32 + ni * 8 + 2 * (lane & 3) + e;
            n_loc[ni * 2 + e] = nl;
            sqn_r[ni * 2 + e] = s_sqn[nl];
            tn_r[ni * 2 + e]  = s_t1[nl];
        }

    u64 rowp[8], colp[8];
#pragma unroll
    for (int i = 0; i < 8; i++) { rowp[i] = ~0ull; colp[i] = ~0ull; }

#pragma unroll
    for (int mi = 0; mi < 4; mi++)
#pragma unroll
        for (int ni = 0; ni < 4; ni++)
#pragma unroll
            for (int h = 0; h < 2; h++)
#pragma unroll
                for (int e = 0; e < 2; e++) {
                    int ri = mi * 2 + h, ci = ni * 2 + e;
                    if (tm_r[ri] != tn_r[ci]) {
                        float d2 = fmaxf(fmaf(-2.f, acc[mi][ni][h * 2 + e],
                                              sqm_r[ri] + sqn_r[ci]), 0.f);
                        u64 hi = (u64)__float_as_uint(d2) << 32;
                        u64 pr = hi | (uint32_t)(BATCH + n0 + n_loc[ci]);
                        u64 pc = hi | (uint32_t)(m0 + m_loc[ri]);
                        if (pr < rowp[ri]) rowp[ri] = pr;
                        if (pc < colp[ci]) colp[ci] = pc;
                    }
                }

    // warp pre-reduce: rows across lane&3, cols across lane>>2
#pragma unroll
    for (int i = 0; i < 8; i++) {
        u64 v = rowp[i];
        u64 w1 = __shfl_xor_sync(0xffffffffu, v, 1);  if (w1 < v) v = w1;
        u64 w2 = __shfl_xor_sync(0xffffffffu, v, 2);  if (w2 < v) v = w2;
        rowp[i] = v;
        u64 c = colp[i];
        u64 c4  = __shfl_xor_sync(0xffffffffu, c, 4);   if (c4  < c) c = c4;
        u64 c8  = __shfl_xor_sync(0xffffffffu, c, 8);   if (c8  < c) c = c8;
        u64 c16 = __shfl_xor_sync(0xffffffffu, c, 16);  if (c16 < c) c = c16;
        colp[i] = c;
    }
    if ((lane & 3) == 0) {
#pragma unroll
        for (int i = 0; i < 8; i++) atomicMin(&s_rmin[m_loc[i]], rowp[i]);
    }
    if (lane < 4) {
#pragma unroll
        for (int i = 0; i < 8; i++) atomicMin(&s_cmin[n_loc[i]], colp[i]);
    }
    __syncthreads();

    if (tid < 128) {
        g_rowmin[m0 + tid][blockIdx.x] = s_rmin[tid];
        g_colmin[n0 + tid][blockIdx.y] = s_cmin[tid];
    }
}

// ---------------------------------------------------------------------------
// Kernel C: exact refinement — one warp per row
// ---------------------------------------------------------------------------
__global__ __launch_bounds__(256) void refine_kernel(const float* __restrict__ X,
                                                     const int* __restrict__ T) {
    const int wid  = (blockIdx.x * blockDim.x + threadIdx.x) >> 5;
    const int lane = threadIdx.x & 31;
    if (wid >= NROWS) return;

    const u64* cand = (wid < BATCH) ? g_rowmin[wid] : g_colmin[wid - BATCH];
    u64 e0 = cand[lane];
    u64 e1 = cand[lane + 32];
    u64 m = (e0 < e1) ? e0 : e1;
#pragma unroll
    for (int k = 16; k; k >>= 1) {
        u64 o = __shfl_xor_sync(0xffffffffu, m, k);
        if (o < m) m = o;
    }
    const float thr = __uint_as_float((uint32_t)(m >> 32)) + W_D2;

    const float4 xr  = reinterpret_cast<const float4*>(X)[(size_t)wid * 32 + lane];
    const float  sqi = g_sq[wid];

    float an = __int_as_float(0x7f800000);
    unsigned b0 = __ballot_sync(0xffffffffu,
                                __uint_as_float((uint32_t)(e0 >> 32)) <= thr);
    unsigned b1 = __ballot_sync(0xffffffffu,
                                __uint_as_float((uint32_t)(e1 >> 32)) <= thr);

    auto exact_d2 = [&](int j) -> float {
        float4 yr = reinterpret_cast<const float4*>(X)[(size_t)j * 32 + lane];
        float s = xr.x * yr.x + xr.y * yr.y + xr.z * yr.z + xr.w * yr.w;
#pragma unroll
        for (int k = 16; k; k >>= 1) s += __shfl_xor_sync(0xffffffffu, s, k);
        return fmaxf(fmaf(-2.f, s, sqi + g_sq[j]), 0.f);
    };

    while (b0) {
        int src = __ffs(b0) - 1;  b0 &= b0 - 1;
        u64 e = __shfl_sync(0xffffffffu, e0, src);
        an = fminf(an, exact_d2((int)(uint32_t)e));
    }
    while (b1) {
        int src = __ffs(b1) - 1;  b1 &= b1 - 1;
        u64 e = __shfl_sync(0xffffffffu, e1, src);
        an = fminf(an, exact_d2((int)(uint32_t)e));
    }

    // exact positives (exhaustive over cross-modal same-label list)
    const int t  = T[wid];
    const int om = (wid < BATCH) ? 1 : 0;
    int cnt = g_cnt[om][t];
    if (cnt > LISTCAP) cnt = LISTCAP;
    float ap = 0.f;
    for (int p = 0; p < cnt; p++) {
        int j = g_list[om][t][p];
        ap = fmaxf(ap, exact_d2(j));
    }

    if (lane == 0) {
        g_apf[wid] = ap;
        g_anf[wid] = an;
    }
}

// ---------------------------------------------------------------------------
// Kernel D: final loss / correct reduction
// ---------------------------------------------------------------------------
__global__ void finalize_kernel(float* __restrict__ out) {
    __shared__ float red[256];
    __shared__ int   redc[256];
    float lsum = 0.f;
    int   cnt  = 0;
    for (int i = threadIdx.x; i < NROWS; i += 256) {
        float ap = sqrtf(fmaxf(g_apf[i], 1e-12f));
        float an = sqrtf(fmaxf(g_anf[i], 1e-12f));
        lsum += fmaxf(ap - an + MARGINF, 0.f);
        cnt  += (an >= ap) ? 1 : 0;
    }
    red[threadIdx.x]  = lsum;
    redc[threadIdx.x] = cnt;
    __syncthreads();
    for (int s = 128; s; s >>= 1) {
        if (threadIdx.x < s) {
            red[threadIdx.x]  += red[threadIdx.x + s];
            redc[threadIdx.x] += redc[threadIdx.x + s];
        }
        __syncthreads();
    }
    if (threadIdx.x == 0) {
        out[0] = red[0] / (float)NROWS;
        out[1] = (float)redc[0];
    }
}

extern "C" void kernel_launch(void* const* d_in, const int* in_sizes, int n_in,
                              void* d_out, int out_size) {
    const float* X = (const float*)d_in[0];
    const int*   T = (const int*)d_in[1];
    float* out = (float*)d_out;

    static bool attr_set = false;
    if (!attr_set) {
        cudaFuncSetAttribute(dist1_kernel,
                             cudaFuncAttributeMaxDynamicSharedMemorySize, SMEM_TOTAL);
        attr_set = true;
    }

    prep_kernel<<<NROWS / 8, 256>>>(X);
    list_kernel<<<NROWS / 256, 256>>>(T);
    dist1_kernel<<<dim3(BATCH / 128, BATCH / 128), 256, SMEM_TOTAL>>>(T);
    refine_kernel<<<NROWS / 8, 256>>>(X, T);
    finalize_kernel<<<1, 256>>>(out);
}

// round 7
// speedup vs baseline: 2.8466x; 1.1924x over previous
#include <cuda_runtime.h>
#include <cuda_bf16.h>
#include <stdint.h>
#include <math.h>

#define BATCH 8192
#define FEAT  128
#define NROWS (2 * BATCH)
#define MARGINF 0.3f
#define NUM_IDS 1000
#define LISTCAP 64
#define W_D2 1.0f
#define NSTRIP 16          // strips of 4 n-tiles
#define STRIPW 4

typedef unsigned long long u64;

// ---------------- device scratch ----------------
__device__ float g_sq[NROWS];
__device__ __nv_bfloat16 g_hi[(size_t)NROWS * FEAT];
__device__ u64  g_rowmin[BATCH][NSTRIP];  // per (mod0-row, strip)
__device__ u64  g_colmin[BATCH][64];      // per (mod1-row, m-tile)
__device__ int  g_cnt[2][NUM_IDS];
__device__ int  g_list[2][NUM_IDS][LISTCAP];
__device__ float g_apf[NROWS];
__device__ float g_anf[NROWS];

// ---------------- helpers ----------------
__device__ __forceinline__ uint32_t sm_u32(const void* p) {
    uint32_t a;
    asm("{ .reg .u64 t; cvta.to.shared.u64 t, %1; cvt.u32.u64 %0, t; }"
        : "=r"(a) : "l"(p));
    return a;
}
__device__ __forceinline__ void cp_async16(uint32_t dst, const void* src) {
    asm volatile("cp.async.cg.shared.global [%0], [%1], 16;"
                 :: "r"(dst), "l"(src));
}
__device__ __forceinline__ void ldsm_x4(uint32_t& r0, uint32_t& r1,
                                        uint32_t& r2, uint32_t& r3, uint32_t a) {
    asm volatile("ldmatrix.sync.aligned.m8n8.x4.shared.b16 {%0,%1,%2,%3}, [%4];"
                 : "=r"(r0), "=r"(r1), "=r"(r2), "=r"(r3) : "r"(a));
}
__device__ __forceinline__ void mma_bf16(float* d, const uint32_t* a,
                                         const uint32_t* b) {
    asm volatile(
        "mma.sync.aligned.m16n8k16.row.col.f32.bf16.bf16.f32 "
        "{%0,%1,%2,%3}, {%4,%5,%6,%7}, {%8,%9}, {%0,%1,%2,%3};"
        : "+f"(d[0]), "+f"(d[1]), "+f"(d[2]), "+f"(d[3])
        : "r"(a[0]), "r"(a[1]), "r"(a[2]), "r"(a[3]), "r"(b[0]), "r"(b[1]));
}

#define ROW_B    80
#define STAGE_B  (128 * ROW_B)           // 10240
#define OFF_A    0                        // 4 fixed A k-slabs
#define OFF_B    (4 * STAGE_B)            // 4-slot B ring
#define OFF_MISC (8 * STAGE_B)            // 81920
// misc: t0[128] sqm[128] t1[4][128] sqn[4][128] cmin u64[128] rmin u64[128]
#define SMEM_TOTAL (OFF_MISC + 512 + 512 + 2048 + 2048 + 1024 + 1024)  // 89088

// ---------------------------------------------------------------------------
// Kernel A: squared norms + bf16 + zero label counters
// ---------------------------------------------------------------------------
__global__ void prep_kernel(const float* __restrict__ inp) {
    int row  = blockIdx.x * 8 + (threadIdx.x >> 5);
    int lane = threadIdx.x & 31;
    float4 v = reinterpret_cast<const float4*>(inp + (size_t)row * FEAT)[lane];
    float s = v.x * v.x + v.y * v.y + v.z * v.z + v.w * v.w;
#pragma unroll
    for (int o = 16; o; o >>= 1) s += __shfl_down_sync(0xffffffffu, s, o);
    if (lane == 0) g_sq[row] = s;

    __nv_bfloat162* ph = reinterpret_cast<__nv_bfloat162*>(g_hi + (size_t)row * FEAT);
    ph[lane * 2 + 0] = __nv_bfloat162(__float2bfloat16(v.x), __float2bfloat16(v.y));
    ph[lane * 2 + 1] = __nv_bfloat162(__float2bfloat16(v.z), __float2bfloat16(v.w));

    int idx = blockIdx.x * blockDim.x + threadIdx.x;
    if (idx < 2 * NUM_IDS) reinterpret_cast<int*>(g_cnt)[idx] = 0;
}

__global__ void list_kernel(const int* __restrict__ T) {
    int i = blockIdx.x * blockDim.x + threadIdx.x;
    if (i >= NROWS) return;
    int t = T[i];
    int mod = (i >= BATCH) ? 1 : 0;
    int slot = atomicAdd(&g_cnt[mod][t], 1);
    if (slot < LISTCAP) g_list[mod][t][slot] = i;
}

// ---------------------------------------------------------------------------
// Kernel B: strip-mined approx distance GEMM.
// Each CTA: A tile (128 rows x K=128) resident; sweeps 4 n-tiles streaming B.
// ---------------------------------------------------------------------------
__global__ __launch_bounds__(256, 2) void dist1_kernel(const int* __restrict__ T) {
    extern __shared__ __align__(16) char sm[];
    int*   s_t0   = reinterpret_cast<int*>(sm + OFF_MISC);
    float* s_sqm  = reinterpret_cast<float*>(sm + OFF_MISC + 512);
    int*   s_t1   = reinterpret_cast<int*>(sm + OFF_MISC + 1024);    // [4][128]
    float* s_sqn  = reinterpret_cast<float*>(sm + OFF_MISC + 3072);  // [4][128]
    u64*   s_cmin = reinterpret_cast<u64*>(sm + OFF_MISC + 5120);
    u64*   s_rmin = reinterpret_cast<u64*>(sm + OFF_MISC + 6144);

    const int tid  = threadIdx.x;
    const int lane = tid & 31;
    const int warp = tid >> 5;
    const int wm   = warp >> 2;
    const int wn   = warp & 3;
    const int m0   = blockIdx.y * 128;
    const int nb0  = blockIdx.x * STRIPW;   // first n-tile index of strip

    if (tid < 128) {
        s_t0[tid]  = T[m0 + tid];
        s_sqm[tid] = g_sq[m0 + tid];
        s_rmin[tid] = ~0ull;
        s_cmin[tid] = ~0ull;
#pragma unroll
        for (int nt = 0; nt < STRIPW; nt++) {
            int n0 = (nb0 + nt) * 128;
            s_t1[nt * 128 + tid]  = T[BATCH + n0 + tid];
            s_sqn[nt * 128 + tid] = g_sq[BATCH + n0 + tid];
        }
    }

    const uint32_t smA = sm_u32(sm) + OFF_A;
    const uint32_t smB = sm_u32(sm) + OFF_B;

    const int ld_r0 = tid >> 2;
    const int ld_c  = tid & 3;
    const uint32_t dA0 = smA + ld_r0 * ROW_B + ld_c * 16;
    const uint32_t dA1 = smA + (ld_r0 + 64) * ROW_B + ld_c * 16;
    const uint32_t dB0 = smB + ld_r0 * ROW_B + ld_c * 16;
    const uint32_t dB1 = smB + (ld_r0 + 64) * ROW_B + ld_c * 16;
    const size_t g0 = (size_t)ld_r0 * FEAT + ld_c * 8;
    const size_t g1 = (size_t)(ld_r0 + 64) * FEAT + ld_c * 8;

    const int a_row = wm * 64 + (lane & 15);
    const int a_kh  = lane >> 4;
    const uint32_t aA = smA + a_row * ROW_B + a_kh * 16;
    const int bq  = lane >> 3;
    const int b_c = bq & 1;
    uint32_t aB[2];
#pragma unroll
    for (int j = 0; j < 2; j++) {
        int n_row = wn * 32 + (2 * j + (bq >> 1)) * 8 + (lane & 7);
        aB[j] = smB + n_row * ROW_B + b_c * 16;
    }

    const __nv_bfloat16* baseA = g_hi + (size_t)m0 * FEAT;

    // B slab source for pipeline unit u (u = nt*4 + kslab)
    auto b_src = [&](int u) -> const __nv_bfloat16* {
        int n0 = (nb0 + (u >> 2)) * 128;
        return g_hi + (size_t)(BATCH + n0) * FEAT + (u & 3) * 32;
    };
    auto issueB = [&](int u) {
        const __nv_bfloat16* Bs = b_src(u);
        const uint32_t so = (uint32_t)(u & 3) * STAGE_B;
        cp_async16(dB0 + so, Bs + g0);
        cp_async16(dB1 + so, Bs + g1);
    };

    // prologue: A (all 4 k-slabs) as group 0, then B0,B1,B2 as groups 1-3
#pragma unroll
    for (int p = 0; p < 4; p++) {
        const __nv_bfloat16* As = baseA + p * 32;
        const uint32_t so = (uint32_t)p * STAGE_B;
        cp_async16(dA0 + so, As + g0);
        cp_async16(dA1 + so, As + g1);
    }
    asm volatile("cp.async.commit_group;");
#pragma unroll
    for (int u = 0; u < 3; u++) {
        issueB(u);
        asm volatile("cp.async.commit_group;");
    }

    // *** FIX: order the tid<128 shared-init writes before ALL threads'
    // fragment-setup reads of s_t0 / s_sqm (R6's race). ***
    __syncthreads();

    // persistent fragment data for epilogues
    int m_loc[8], n_base[8];
    float sqm_r[8];
    int   tm_r[8];
#pragma unroll
    for (int mi = 0; mi < 4; mi++)
#pragma unroll
        for (int h = 0; h < 2; h++) {
            int ml = wm * 64 + mi * 16 + (lane >> 2) + 8 * h;
            m_loc[mi * 2 + h] = ml;
            sqm_r[mi * 2 + h] = s_sqm[ml];
            tm_r[mi * 2 + h]  = s_t0[ml];
        }
#pragma unroll
    for (int ni = 0; ni < 4; ni++)
#pragma unroll
        for (int e = 0; e < 2; e++)
            n_base[ni * 2 + e] = wn * 32 + ni * 8 + 2 * (lane & 3) + e;

    u64 rowp[8];
#pragma unroll
    for (int i = 0; i < 8; i++) rowp[i] = ~0ull;

    float acc[4][4][4];
#pragma unroll
    for (int mi = 0; mi < 4; mi++)
#pragma unroll
        for (int ni = 0; ni < 4; ni++)
#pragma unroll
            for (int e = 0; e < 4; e++) acc[mi][ni][e] = 0.f;

    for (int u = 0; u < 16; u++) {
        asm volatile("cp.async.wait_group 2;");
        __syncthreads();   // B_u ready; everyone done with slot (u-1)&3

        if (u + 3 < 16) issueB(u + 3);
        asm volatile("cp.async.commit_group;");

        const uint32_t so = (uint32_t)(u & 3) * STAGE_B;
#pragma unroll
        for (int ks = 0; ks < 2; ks++) {
            uint32_t a[4][4], b[4][2];
#pragma unroll
            for (int mi = 0; mi < 4; mi++)
                ldsm_x4(a[mi][0], a[mi][1], a[mi][2], a[mi][3],
                        aA + so + mi * (16 * ROW_B) + ks * 32);
#pragma unroll
            for (int j = 0; j < 2; j++) {
                uint32_t r0, r1, r2, r3;
                ldsm_x4(r0, r1, r2, r3, aB[j] + so + ks * 32);
                b[2 * j + 0][0] = r0;  b[2 * j + 0][1] = r1;
                b[2 * j + 1][0] = r2;  b[2 * j + 1][1] = r3;
            }
#pragma unroll
            for (int mi = 0; mi < 4; mi++)
#pragma unroll
                for (int ni = 0; ni < 4; ni++)
                    mma_bf16(acc[mi][ni], a[mi], b[ni]);
        }

        // ---- n-tile epilogue every 4th unit ----
        if ((u & 3) == 3) {
            const int nt = u >> 2;
            const int n0 = (nb0 + nt) * 128;
            u64 colp[8];
            float sqn_r[8];
            int   tn_r[8];
#pragma unroll
            for (int i = 0; i < 8; i++) {
                colp[i]  = ~0ull;
                sqn_r[i] = s_sqn[nt * 128 + n_base[i]];
                tn_r[i]  = s_t1[nt * 128 + n_base[i]];
            }
#pragma unroll
            for (int mi = 0; mi < 4; mi++)
#pragma unroll
                for (int ni = 0; ni < 4; ni++)
#pragma unroll
                    for (int h = 0; h < 2; h++)
#pragma unroll
                        for (int e = 0; e < 2; e++) {
                            int ri = mi * 2 + h, ci = ni * 2 + e;
                            if (tm_r[ri] != tn_r[ci]) {
                                float d2 = fmaxf(fmaf(-2.f, acc[mi][ni][h * 2 + e],
                                                      sqm_r[ri] + sqn_r[ci]), 0.f);
                                u64 hi = (u64)__float_as_uint(d2) << 32;
                                u64 pr = hi | (uint32_t)(BATCH + n0 + n_base[ci]);
                                u64 pc = hi | (uint32_t)(m0 + m_loc[ri]);
                                if (pr < rowp[ri]) rowp[ri] = pr;
                                if (pc < colp[ci]) colp[ci] = pc;
                            }
                            acc[mi][ni][h * 2 + e] = 0.f;   // reset for next tile
                        }
            // col reduce: across lane>>2 (xor 4,8,16)
#pragma unroll
            for (int i = 0; i < 8; i++) {
                u64 c = colp[i];
                u64 c4  = __shfl_xor_sync(0xffffffffu, c, 4);   if (c4  < c) c = c4;
                u64 c8  = __shfl_xor_sync(0xffffffffu, c, 8);   if (c8  < c) c = c8;
                u64 c16 = __shfl_xor_sync(0xffffffffu, c, 16);  if (c16 < c) c = c16;
                colp[i] = c;
            }
            if (lane < 4) {
#pragma unroll
                for (int i = 0; i < 8; i++) atomicMin(&s_cmin[n_base[i]], colp[i]);
            }
            __syncthreads();
            if (tid < 128) {
                g_colmin[n0 + tid][blockIdx.y] = s_cmin[tid];
                s_cmin[tid] = ~0ull;
            }
            // reset ordered before next tile's atomics by the next
            // top-of-loop __syncthreads.
        }
    }

    // ---- strip end: row mins ----
#pragma unroll
    for (int i = 0; i < 8; i++) {
        u64 v = rowp[i];
        u64 w1 = __shfl_xor_sync(0xffffffffu, v, 1);  if (w1 < v) v = w1;
        u64 w2 = __shfl_xor_sync(0xffffffffu, v, 2);  if (w2 < v) v = w2;
        rowp[i] = v;
    }
    if ((lane & 3) == 0) {
#pragma unroll
        for (int i = 0; i < 8; i++) atomicMin(&s_rmin[m_loc[i]], rowp[i]);
    }
    __syncthreads();
    if (tid < 128) g_rowmin[m0 + tid][blockIdx.x] = s_rmin[tid];
}

// ---------------------------------------------------------------------------
// Kernel C: exact refinement — one warp per row
// ---------------------------------------------------------------------------
__global__ __launch_bounds__(256) void refine_kernel(const float* __restrict__ X,
                                                     const int* __restrict__ T) {
    const int wid  = (blockIdx.x * blockDim.x + threadIdx.x) >> 5;
    const int lane = threadIdx.x & 31;
    if (wid >= NROWS) return;

    u64 e0, e1;
    if (wid < BATCH) {
        e0 = (lane < NSTRIP) ? g_rowmin[wid][lane] : ~0ull;
        e1 = ~0ull;
    } else {
        e0 = g_colmin[wid - BATCH][lane];
        e1 = g_colmin[wid - BATCH][lane + 32];
    }
    u64 m = (e0 < e1) ? e0 : e1;
#pragma unroll
    for (int k = 16; k; k >>= 1) {
        u64 o = __shfl_xor_sync(0xffffffffu, m, k);
        if (o < m) m = o;
    }
    const float thr = __uint_as_float((uint32_t)(m >> 32)) + W_D2;

    const float4 xr  = reinterpret_cast<const float4*>(X)[(size_t)wid * 32 + lane];
    const float  sqi = g_sq[wid];

    float an = __int_as_float(0x7f800000);
    unsigned b0 = __ballot_sync(0xffffffffu,
                                __uint_as_float((uint32_t)(e0 >> 32)) <= thr);
    unsigned b1 = __ballot_sync(0xffffffffu,
                                __uint_as_float((uint32_t)(e1 >> 32)) <= thr);

    auto exact_d2 = [&](int j) -> float {
        float4 yr = reinterpret_cast<const float4*>(X)[(size_t)j * 32 + lane];
        float s = xr.x * yr.x + xr.y * yr.y + xr.z * yr.z + xr.w * yr.w;
#pragma unroll
        for (int k = 16; k; k >>= 1) s += __shfl_xor_sync(0xffffffffu, s, k);
        return fmaxf(fmaf(-2.f, s, sqi + g_sq[j]), 0.f);
    };

    while (b0) {
        int src = __ffs(b0) - 1;  b0 &= b0 - 1;
        u64 e = __shfl_sync(0xffffffffu, e0, src);
        an = fminf(an, exact_d2((int)(uint32_t)e));
    }
    while (b1) {
        int src = __ffs(b1) - 1;  b1 &= b1 - 1;
        u64 e = __shfl_sync(0xffffffffu, e1, src);
        an = fminf(an, exact_d2((int)(uint32_t)e));
    }

    const int t  = T[wid];
    const int om = (wid < BATCH) ? 1 : 0;
    int cnt = g_cnt[om][t];
    if (cnt > LISTCAP) cnt = LISTCAP;
    float ap = 0.f;
    for (int p = 0; p < cnt; p++) {
        int j = g_list[om][t][p];
        ap = fmaxf(ap, exact_d2(j));
    }

    if (lane == 0) {
        g_apf[wid] = ap;
        g_anf[wid] = an;
    }
}

// ---------------------------------------------------------------------------
// Kernel D: final loss / correct reduction (1024 threads, float4 loads)
// ---------------------------------------------------------------------------
__global__ void finalize_kernel(float* __restrict__ out) {
    __shared__ float red[1024];
    __shared__ int   redc[1024];
    float lsum = 0.f;
    int   cnt  = 0;
    const float4* ap4 = reinterpret_cast<const float4*>(g_apf);
    const float4* an4 = reinterpret_cast<const float4*>(g_anf);
    for (int i = threadIdx.x; i < NROWS / 4; i += 1024) {
        float4 a = ap4[i];
        float4 n = an4[i];
        float apv[4] = {a.x, a.y, a.z, a.w};
        float anv[4] = {n.x, n.y, n.z, n.w};
#pragma unroll
        for (int k = 0; k < 4; k++) {
            float ap = sqrtf(fmaxf(apv[k], 1e-12f));
            float an = sqrtf(fmaxf(anv[k], 1e-12f));
            lsum += fmaxf(ap - an + MARGINF, 0.f);
            cnt  += (an >= ap) ? 1 : 0;
        }
    }
    red[threadIdx.x]  = lsum;
    redc[threadIdx.x] = cnt;
    __syncthreads();
    for (int s = 512; s; s >>= 1) {
        if (threadIdx.x < s) {
            red[threadIdx.x]  += red[threadIdx.x + s];
            redc[threadIdx.x] += redc[threadIdx.x + s];
        }
        __syncthreads();
    }
    if (threadIdx.x == 0) {
        out[0] = red[0] / (float)NROWS;
        out[1] = (float)redc[0];
    }
}

extern "C" void kernel_launch(void* const* d_in, const int* in_sizes, int n_in,
                              void* d_out, int out_size) {
    const float* X = (const float*)d_in[0];
    const int*   T = (const int*)d_in[1];
    float* out = (float*)d_out;

    static bool attr_set = false;
    if (!attr_set) {
        cudaFuncSetAttribute(dist1_kernel,
                             cudaFuncAttributeMaxDynamicSharedMemorySize, SMEM_TOTAL);
        attr_set = true;
    }

    prep_kernel<<<NROWS / 8, 256>>>(X);
    list_kernel<<<NROWS / 256, 256>>>(T);
    dist1_kernel<<<dim3(NSTRIP, BATCH / 128), 256, SMEM_TOTAL>>>(T);
    refine_kernel<<<NROWS / 8, 256>>>(X, T);
    finalize_kernel<<<1, 1024>>>(out);
}

// round 10
// speedup vs baseline: 2.8785x; 1.0112x over previous
#include <cuda_runtime.h>
#include <cuda_bf16.h>
#include <stdint.h>
#include <math.h>

#define BATCH 8192
#define FEAT  128
#define NROWS (2 * BATCH)
#define MARGINF 0.3f
#define NUM_IDS 1000
#define LISTCAP 64
#define W_D2 1.0f
#define NSTRIP 16          // strips of 4 n-tiles
#define STRIPW 4

typedef unsigned long long u64;

// ---------------- device scratch ----------------
__device__ float g_sq[NROWS];
__device__ __nv_bfloat16 g_hi[(size_t)NROWS * FEAT];
__device__ u64  g_rowmin[BATCH][NSTRIP];  // per (mod0-row, strip)
__device__ u64  g_colmin[BATCH][64];      // per (mod1-row, m-tile)
__device__ int  g_cnt[2][NUM_IDS];
__device__ int  g_list[2][NUM_IDS][LISTCAP];
__device__ float g_apf[NROWS];
__device__ float g_anf[NROWS];

// ---------------- helpers ----------------
__device__ __forceinline__ uint32_t sm_u32(const void* p) {
    uint32_t a;
    asm("{ .reg .u64 t; cvta.to.shared.u64 t, %1; cvt.u32.u64 %0, t; }"
        : "=r"(a) : "l"(p));
    return a;
}
__device__ __forceinline__ void cp_async16(uint32_t dst, const void* src) {
    asm volatile("cp.async.cg.shared.global [%0], [%1], 16;"
                 :: "r"(dst), "l"(src));
}
__device__ __forceinline__ void ldsm_x4(uint32_t& r0, uint32_t& r1,
                                        uint32_t& r2, uint32_t& r3, uint32_t a) {
    asm volatile("ldmatrix.sync.aligned.m8n8.x4.shared.b16 {%0,%1,%2,%3}, [%4];"
                 : "=r"(r0), "=r"(r1), "=r"(r2), "=r"(r3) : "r"(a));
}
__device__ __forceinline__ void mma_bf16(float* d, const uint32_t* a,
                                         const uint32_t* b) {
    asm volatile(
        "mma.sync.aligned.m16n8k16.row.col.f32.bf16.bf16.f32 "
        "{%0,%1,%2,%3}, {%4,%5,%6,%7}, {%8,%9}, {%0,%1,%2,%3};"
        : "+f"(d[0]), "+f"(d[1]), "+f"(d[2]), "+f"(d[3])
        : "r"(a[0]), "r"(a[1]), "r"(a[2]), "r"(a[3]), "r"(b[0]), "r"(b[1]));
}

#define ROW_B    80
#define STAGE_B  (128 * ROW_B)           // 10240
#define NRING    6
#define OFF_A    0                        // 4 fixed A k-slabs: 40960
#define OFF_B    (4 * STAGE_B)            // 6-slot B ring: 61440
#define OFF_MISC ((4 + NRING) * STAGE_B)  // 102400
// misc: t0[128] sqm[128] t1[4][128] sqn[4][128] cmin u64[128] rmin u64[128]
#define SMEM_TOTAL (OFF_MISC + 512 + 512 + 2048 + 2048 + 1024 + 1024)  // 109568

// ---------------------------------------------------------------------------
// Kernel A: squared norms + bf16 + zero label counters
// ---------------------------------------------------------------------------
__global__ void prep_kernel(const float* __restrict__ inp) {
    int row  = blockIdx.x * 8 + (threadIdx.x >> 5);
    int lane = threadIdx.x & 31;
    float4 v = reinterpret_cast<const float4*>(inp + (size_t)row * FEAT)[lane];
    float s = v.x * v.x + v.y * v.y + v.z * v.z + v.w * v.w;
#pragma unroll
    for (int o = 16; o; o >>= 1) s += __shfl_down_sync(0xffffffffu, s, o);
    if (lane == 0) g_sq[row] = s;

    __nv_bfloat162* ph = reinterpret_cast<__nv_bfloat162*>(g_hi + (size_t)row * FEAT);
    ph[lane * 2 + 0] = __nv_bfloat162(__float2bfloat16(v.x), __float2bfloat16(v.y));
    ph[lane * 2 + 1] = __nv_bfloat162(__float2bfloat16(v.z), __float2bfloat16(v.w));

    int idx = blockIdx.x * blockDim.x + threadIdx.x;
    if (idx < 2 * NUM_IDS) reinterpret_cast<int*>(g_cnt)[idx] = 0;
}

__global__ void list_kernel(const int* __restrict__ T) {
    int i = blockIdx.x * blockDim.x + threadIdx.x;
    if (i >= NROWS) return;
    int t = T[i];
    int mod = (i >= BATCH) ? 1 : 0;
    int slot = atomicAdd(&g_cnt[mod][t], 1);
    if (slot < LISTCAP) g_list[mod][t][slot] = i;
}

// ---------------------------------------------------------------------------
// Kernel B: strip-mined approx distance GEMM (negatives argmin mining).
// FIX vs R9: A k-slab offset (u&3) decoupled from B ring slot (u%NRING).
// ---------------------------------------------------------------------------
__global__ __launch_bounds__(256, 2) void dist1_kernel(const int* __restrict__ T) {
    extern __shared__ __align__(16) char sm[];
    int*   s_t0   = reinterpret_cast<int*>(sm + OFF_MISC);
    float* s_sqm  = reinterpret_cast<float*>(sm + OFF_MISC + 512);
    int*   s_t1   = reinterpret_cast<int*>(sm + OFF_MISC + 1024);    // [4][128]
    float* s_sqn  = reinterpret_cast<float*>(sm + OFF_MISC + 3072);  // [4][128]
    u64*   s_cmin = reinterpret_cast<u64*>(sm + OFF_MISC + 5120);
    u64*   s_rmin = reinterpret_cast<u64*>(sm + OFF_MISC + 6144);

    const int tid  = threadIdx.x;
    const int lane = tid & 31;
    const int warp = tid >> 5;
    const int wm   = warp >> 2;
    const int wn   = warp & 3;
    const int m0   = blockIdx.y * 128;
    const int nb0  = blockIdx.x * STRIPW;

    if (tid < 128) {
        s_t0[tid]  = T[m0 + tid];
        s_sqm[tid] = g_sq[m0 + tid];
        s_rmin[tid] = ~0ull;
        s_cmin[tid] = ~0ull;
#pragma unroll
        for (int nt = 0; nt < STRIPW; nt++) {
            int n0 = (nb0 + nt) * 128;
            s_t1[nt * 128 + tid]  = T[BATCH + n0 + tid];
            s_sqn[nt * 128 + tid] = g_sq[BATCH + n0 + tid];
        }
    }

    const uint32_t smA = sm_u32(sm) + OFF_A;
    const uint32_t smB = sm_u32(sm) + OFF_B;

    const int ld_r0 = tid >> 2;
    const int ld_c  = tid & 3;
    const uint32_t dA0 = smA + ld_r0 * ROW_B + ld_c * 16;
    const uint32_t dA1 = smA + (ld_r0 + 64) * ROW_B + ld_c * 16;
    const uint32_t dB0 = smB + ld_r0 * ROW_B + ld_c * 16;
    const uint32_t dB1 = smB + (ld_r0 + 64) * ROW_B + ld_c * 16;
    const size_t g0 = (size_t)ld_r0 * FEAT + ld_c * 8;
    const size_t g1 = (size_t)(ld_r0 + 64) * FEAT + ld_c * 8;

    const int a_row = wm * 64 + (lane & 15);
    const int a_kh  = lane >> 4;
    const uint32_t aA = smA + a_row * ROW_B + a_kh * 16;
    const int bq  = lane >> 3;
    const int b_c = bq & 1;
    uint32_t aB[2];
#pragma unroll
    for (int j = 0; j < 2; j++) {
        int n_row = wn * 32 + (2 * j + (bq >> 1)) * 8 + (lane & 7);
        aB[j] = smB + n_row * ROW_B + b_c * 16;
    }

    const __nv_bfloat16* baseA = g_hi + (size_t)m0 * FEAT;

    auto issueB = [&](int u) {
        int n0 = (nb0 + (u >> 2)) * 128;
        const __nv_bfloat16* Bs = g_hi + (size_t)(BATCH + n0) * FEAT + (u & 3) * 32;
        const uint32_t so = (uint32_t)(u % NRING) * STAGE_B;
        cp_async16(dB0 + so, Bs + g0);
        cp_async16(dB1 + so, Bs + g1);
    };

    // prologue: A (group 0), then B0..B4 (groups 1..5)
#pragma unroll
    for (int p = 0; p < 4; p++) {
        const __nv_bfloat16* As = baseA + p * 32;
        const uint32_t so = (uint32_t)p * STAGE_B;
        cp_async16(dA0 + so, As + g0);
        cp_async16(dA1 + so, As + g1);
    }
    asm volatile("cp.async.commit_group;");
#pragma unroll
    for (int u = 0; u < NRING - 1; u++) {
        issueB(u);
        asm volatile("cp.async.commit_group;");
    }

    __syncthreads();   // shared-init writes visible before fragment setup reads

    int m_loc[8], n_base[8];
    float sqm_r[8];
    int   tm_r[8];
#pragma unroll
    for (int mi = 0; mi < 4; mi++)
#pragma unroll
        for (int h = 0; h < 2; h++) {
            int ml = wm * 64 + mi * 16 + (lane >> 2) + 8 * h;
            m_loc[mi * 2 + h] = ml;
            sqm_r[mi * 2 + h] = s_sqm[ml];
            tm_r[mi * 2 + h]  = s_t0[ml];
        }
#pragma unroll
    for (int ni = 0; ni < 4; ni++)
#pragma unroll
        for (int e = 0; e < 2; e++)
            n_base[ni * 2 + e] = wn * 32 + ni * 8 + 2 * (lane & 3) + e;

    u64 rowp[8];
#pragma unroll
    for (int i = 0; i < 8; i++) rowp[i] = ~0ull;

    float acc[4][4][4];
#pragma unroll
    for (int mi = 0; mi < 4; mi++)
#pragma unroll
        for (int ni = 0; ni < 4; ni++)
#pragma unroll
            for (int e = 0; e < 4; e++) acc[mi][ni][e] = 0.f;

#pragma unroll
    for (int u = 0; u < 16; u++) {
        // group for B_u = index u+1; wait_group 4 completes it (newest 4 pending)
        asm volatile("cp.async.wait_group 4;");
        __syncthreads();

        if (u + NRING - 1 < 16) issueB(u + NRING - 1);
        asm volatile("cp.async.commit_group;");

        // *** FIX: A uses k-slab offset (u&3); B uses ring-slot offset (u%NRING) ***
        const uint32_t soA = (uint32_t)(u & 3) * STAGE_B;
        const uint32_t soB = (uint32_t)(u % NRING) * STAGE_B;
#pragma unroll
        for (int ks = 0; ks < 2; ks++) {
            uint32_t a[4][4], b[4][2];
#pragma unroll
            for (int mi = 0; mi < 4; mi++)
                ldsm_x4(a[mi][0], a[mi][1], a[mi][2], a[mi][3],
                        aA + soA + mi * (16 * ROW_B) + ks * 32);
#pragma unroll
            for (int j = 0; j < 2; j++) {
                uint32_t r0, r1, r2, r3;
                ldsm_x4(r0, r1, r2, r3, aB[j] + soB + ks * 32);
                b[2 * j + 0][0] = r0;  b[2 * j + 0][1] = r1;
                b[2 * j + 1][0] = r2;  b[2 * j + 1][1] = r3;
            }
#pragma unroll
            for (int mi = 0; mi < 4; mi++)
#pragma unroll
                for (int ni = 0; ni < 4; ni++)
                    mma_bf16(acc[mi][ni], a[mi], b[ni]);
        }

        // ---- n-tile epilogue every 4th unit ----
        if ((u & 3) == 3) {
            const int nt = u >> 2;
            const int n0 = (nb0 + nt) * 128;
            u64 colp[8];
            float sqn_r[8];
            int   tn_r[8];
#pragma unroll
            for (int i = 0; i < 8; i++) {
                colp[i]  = ~0ull;
                sqn_r[i] = s_sqn[nt * 128 + n_base[i]];
                tn_r[i]  = s_t1[nt * 128 + n_base[i]];
            }
#pragma unroll
            for (int mi = 0; mi < 4; mi++)
#pragma unroll
                for (int ni = 0; ni < 4; ni++)
#pragma unroll
                    for (int h = 0; h < 2; h++)
#pragma unroll
                        for (int e = 0; e < 2; e++) {
                            int ri = mi * 2 + h, ci = ni * 2 + e;
                            if (tm_r[ri] != tn_r[ci]) {
                                float d2 = fmaxf(fmaf(-2.f, acc[mi][ni][h * 2 + e],
                                                      sqm_r[ri] + sqn_r[ci]), 0.f);
                                u64 hi = (u64)__float_as_uint(d2) << 32;
                                u64 pr = hi | (uint32_t)(BATCH + n0 + n_base[ci]);
                                u64 pc = hi | (uint32_t)(m0 + m_loc[ri]);
                                if (pr < rowp[ri]) rowp[ri] = pr;
                                if (pc < colp[ci]) colp[ci] = pc;
                            }
                            acc[mi][ni][h * 2 + e] = 0.f;   // reset for next tile
                        }
#pragma unroll
            for (int i = 0; i < 8; i++) {
                u64 c = colp[i];
                u64 c4  = __shfl_xor_sync(0xffffffffu, c, 4);   if (c4  < c) c = c4;
                u64 c8  = __shfl_xor_sync(0xffffffffu, c, 8);   if (c8  < c) c = c8;
                u64 c16 = __shfl_xor_sync(0xffffffffu, c, 16);  if (c16 < c) c = c16;
                colp[i] = c;
            }
            if (lane < 4) {
#pragma unroll
                for (int i = 0; i < 8; i++) atomicMin(&s_cmin[n_base[i]], colp[i]);
            }
            __syncthreads();
            if (tid < 128) {
                g_colmin[n0 + tid][blockIdx.y] = s_cmin[tid];
                s_cmin[tid] = ~0ull;
            }
            // reset ordered before next tile's atomics by next top-of-loop barrier
        }
    }

    // ---- strip end: row mins ----
#pragma unroll
    for (int i = 0; i < 8; i++) {
        u64 v = rowp[i];
        u64 w1 = __shfl_xor_sync(0xffffffffu, v, 1);  if (w1 < v) v = w1;
        u64 w2 = __shfl_xor_sync(0xffffffffu, v, 2);  if (w2 < v) v = w2;
        rowp[i] = v;
    }
    if ((lane & 3) == 0) {
#pragma unroll
        for (int i = 0; i < 8; i++) atomicMin(&s_rmin[m_loc[i]], rowp[i]);
    }
    __syncthreads();
    if (tid < 128) g_rowmin[m0 + tid][blockIdx.x] = s_rmin[tid];
}

// ---------------------------------------------------------------------------
// Kernel C: exact refinement — one warp per row (R7-proven)
// ---------------------------------------------------------------------------
__global__ __launch_bounds__(256) void refine_kernel(const float* __restrict__ X,
                                                     const int* __restrict__ T) {
    const int wid  = (blockIdx.x * blockDim.x + threadIdx.x) >> 5;
    const int lane = threadIdx.x & 31;
    if (wid >= NROWS) return;

    u64 e0, e1;
    if (wid < BATCH) {
        e0 = (lane < NSTRIP) ? g_rowmin[wid][lane] : ~0ull;
        e1 = ~0ull;
    } else {
        e0 = g_colmin[wid - BATCH][lane];
        e1 = g_colmin[wid - BATCH][lane + 32];
    }
    u64 m = (e0 < e1) ? e0 : e1;
#pragma unroll
    for (int k = 16; k; k >>= 1) {
        u64 o = __shfl_xor_sync(0xffffffffu, m, k);
        if (o < m) m = o;
    }
    const float thr = __uint_as_float((uint32_t)(m >> 32)) + W_D2;

    const float4 xr  = reinterpret_cast<const float4*>(X)[(size_t)wid * 32 + lane];
    const float  sqi = g_sq[wid];

    float an = __int_as_float(0x7f800000);
    unsigned b0 = __ballot_sync(0xffffffffu,
                                __uint_as_float((uint32_t)(e0 >> 32)) <= thr);
    unsigned b1 = __ballot_sync(0xffffffffu,
                                __uint_as_float((uint32_t)(e1 >> 32)) <= thr);

    auto exact_d2 = [&](int j) -> float {
        float4 yr = reinterpret_cast<const float4*>(X)[(size_t)j * 32 + lane];
        float s = xr.x * yr.x + xr.y * yr.y + xr.z * yr.z + xr.w * yr.w;
#pragma unroll
        for (int k = 16; k; k >>= 1) s += __shfl_xor_sync(0xffffffffu, s, k);
        return fmaxf(fmaf(-2.f, s, sqi + g_sq[j]), 0.f);
    };

    while (b0) {
        int src = __ffs(b0) - 1;  b0 &= b0 - 1;
        u64 e = __shfl_sync(0xffffffffu, e0, src);
        an = fminf(an, exact_d2((int)(uint32_t)e));
    }
    while (b1) {
        int src = __ffs(b1) - 1;  b1 &= b1 - 1;
        u64 e = __shfl_sync(0xffffffffu, e1, src);
        an = fminf(an, exact_d2((int)(uint32_t)e));
    }

    const int t  = T[wid];
    const int om = (wid < BATCH) ? 1 : 0;
    int cnt = g_cnt[om][t];
    if (cnt > LISTCAP) cnt = LISTCAP;
    float ap = 0.f;
    for (int p = 0; p < cnt; p++) {
        int j = g_list[om][t][p];
        ap = fmaxf(ap, exact_d2(j));
    }

    if (lane == 0) {
        g_apf[wid] = ap;
        g_anf[wid] = an;
    }
}

// ---------------------------------------------------------------------------
// Kernel D: final loss / correct reduction (1024 threads, float4 loads)
// ---------------------------------------------------------------------------
__global__ void finalize_kernel(float* __restrict__ out) {
    __shared__ float red[1024];
    __shared__ int   redc[1024];
    float lsum = 0.f;
    int   cnt  = 0;
    const float4* ap4 = reinterpret_cast<const float4*>(g_apf);
    const float4* an4 = reinterpret_cast<const float4*>(g_anf);
    for (int i = threadIdx.x; i < NROWS / 4; i += 1024) {
        float4 a = ap4[i];
        float4 n = an4[i];
        float apv[4] = {a.x, a.y, a.z, a.w};
        float anv[4] = {n.x, n.y, n.z, n.w};
#pragma unroll
        for (int k = 0; k < 4; k++) {
            float ap = sqrtf(fmaxf(apv[k], 1e-12f));
            float an = sqrtf(fmaxf(anv[k], 1e-12f));
            lsum += fmaxf(ap - an + MARGINF, 0.f);
            cnt  += (an >= ap) ? 1 : 0;
        }
    }
    red[threadIdx.x]  = lsum;
    redc[threadIdx.x] = cnt;
    __syncthreads();
    for (int s = 512; s; s >>= 1) {
        if (threadIdx.x < s) {
            red[threadIdx.x]  += red[threadIdx.x + s];
            redc[threadIdx.x] += redc[threadIdx.x + s];
        }
        __syncthreads();
    }
    if (threadIdx.x == 0) {
        out[0] = red[0] / (float)NROWS;
        out[1] = (float)redc[0];
    }
}

extern "C" void kernel_launch(void* const* d_in, const int* in_sizes, int n_in,
                              void* d_out, int out_size) {
    const float* X = (const float*)d_in[0];
    const int*   T = (const int*)d_in[1];
    float* out = (float*)d_out;

    static bool attr_set = false;
    if (!attr_set) {
        cudaFuncSetAttribute(dist1_kernel,
                             cudaFuncAttributeMaxDynamicSharedMemorySize, SMEM_TOTAL);
        attr_set = true;
    }

    prep_kernel<<<NROWS / 8, 256>>>(X);
    list_kernel<<<NROWS / 256, 256>>>(T);
    dist1_kernel<<<dim3(NSTRIP, BATCH / 128), 256, SMEM_TOTAL>>>(T);
    refine_kernel<<<NROWS / 8, 256>>>(X, T);
    finalize_kernel<<<1, 1024>>>(out);
}